// round 14
// baseline (speedup 1.0000x reference)
#include <cuda_runtime.h>
#include <cuda.h>
#include <cuda_bf16.h>
#include <cstdint>

// Arch-feature gate: tcgen05/TMA path only in the sm_103a cubin pass. The
// compute_103 PTX pass compiles the mma.sync fallback (never executed).
#if defined(__CUDA_ARCH__) && defined(__CUDA_ARCH_HAS_FEATURE__)
#if __CUDA_ARCH_HAS_FEATURE__(SM103_ALL)
#define HAS_TC 1
#else
#define HAS_TC 0
#endif
#else
#define HAS_TC 0
#endif

// ---------------- problem dims (fixed by setup_inputs) ----------------
namespace cfg {
constexpr int M = 8192;     // B*S
constexpr int N = 4096;     // D_OUT
constexpr int K = 4096;     // D_IN
constexpr int BM = 256, BN = 256, BK = 64;       // per 2-CTA pair
constexpr int STAGES = 5;
constexpr int NK = K / BK;                       // 64
constexpr int NT_N = N / BN;                     // 16
constexpr int NTILES = (M / BM) * NT_N;          // 512
constexpr int NPAIRS = 74;                       // 148 SMs / 2
constexpr int A_SLICE = 128 * BK * 2;            // 16384 (per-CTA A rows)
constexpr int B_SLICE = 128 * BK * 2;            // 16384 (per-CTA B rows, N/2)
constexpr int STAGE_BYTES = A_SLICE + B_SLICE;   // 32768
constexpr int SMEM_TILE = 1024;
constexpr int SMEM_EPI  = SMEM_TILE + STAGES * STAGE_BYTES;   // 164864
constexpr int SMEM_LBS  = SMEM_EPI + 8 * 32 * 33 * 4;         // 198656
constexpr int SMEM_TOTAL = SMEM_LBS + 8 * 288 * 4;            // 207872
constexpr int MBAR_FULL = 64;                    // 5 x 8B
constexpr int MBAR_DONE = 112;                   // 5 x 8B
constexpr int MBAR_FIN  = 160;                   // 2 x 8B
constexpr int MBAR_EPI  = 176;                   // 2 x 8B
constexpr int NTHREADS = 320;                    // 8 epi warps + consumer + producer
// cg2 idesc: M_TOTAL=256 x N=256 kind::f16 bf16
constexpr uint32_t IDESC = 0x10u | 0x80u | 0x400u | ((256 / 8) << 17) | ((256 / 16) << 24);
}

// ---------------- scratch ----------------
__device__ __nv_bfloat16 g_X [(size_t)cfg::M * cfg::K];   // x in bf16, [M][K]
__device__ __nv_bfloat16 g_Wt[(size_t)cfg::N * cfg::K];   // W^T bf16, [N][K] K-major
__device__ float         g_H [cfg::M * 8];                // LoRA hidden

__constant__ float c_nf4[16] = {
    -1.0f, -0.6962f, -0.5251f, -0.3949f, -0.2844f, -0.1848f, -0.0911f, 0.0f,
     0.0796f, 0.1609f, 0.2461f, 0.3379f, 0.4407f, 0.5626f, 0.723f, 1.0f};

// ---------------- generic helpers ----------------
__device__ __forceinline__ uint32_t smem_u32(const void* p) {
    return (uint32_t)__cvta_generic_to_shared(p);
}
__device__ __forceinline__ void cp_async16(uint32_t s, const void* g) {
    asm volatile("cp.async.cg.shared.global [%0], [%1], 16;" :: "r"(s), "l"(g));
}
__device__ __forceinline__ void cp_commit() { asm volatile("cp.async.commit_group;"); }
template <int W>
__device__ __forceinline__ void cp_wait() {
    asm volatile("cp.async.wait_group %0;" :: "n"(W));
}
__device__ __forceinline__ uint32_t sw128(uint32_t b) { return b ^ ((b >> 3) & 0x70); }

__device__ __forceinline__ void ldsm_x4(uint32_t a[4], uint32_t addr) {
    asm volatile("ldmatrix.sync.aligned.m8n8.x4.shared.b16 {%0,%1,%2,%3}, [%4];"
                 : "=r"(a[0]), "=r"(a[1]), "=r"(a[2]), "=r"(a[3]) : "r"(addr));
}
__device__ __forceinline__ void mma16816(float d[4], const uint32_t a[4],
                                         uint32_t b0, uint32_t b1) {
    asm volatile(
        "mma.sync.aligned.m16n8k16.row.col.f32.bf16.bf16.f32 "
        "{%0,%1,%2,%3}, {%4,%5,%6,%7}, {%8,%9}, {%0,%1,%2,%3};"
        : "+f"(d[0]), "+f"(d[1]), "+f"(d[2]), "+f"(d[3])
        : "r"(a[0]), "r"(a[1]), "r"(a[2]), "r"(a[3]), "r"(b0), "r"(b1));
}

#if HAS_TC
// ---------------- tcgen05/TMA helpers (sm_103a pass only) ----------------
__device__ __forceinline__ uint64_t make_desc(uint32_t addr) {
    constexpr uint64_t BASE =
        (uint64_t(2) << 61) | (uint64_t(1) << 46) | (uint64_t(64) << 32) | (uint64_t(1) << 16);
    return BASE | ((uint64_t)(addr >> 4) & 0x3FFF);
}
__device__ __forceinline__ void mma_f16_ss_cg2(uint32_t d, uint64_t a, uint64_t b,
                                               uint32_t idesc, uint32_t en) {
    asm volatile(
        "{\n\t.reg .pred p;\n\tsetp.ne.u32 p, %5, 0;\n\t"
        "tcgen05.mma.cta_group::2.kind::f16 [%0], %1, %2, %3, "
        "{%4, %4, %4, %4, %4, %4, %4, %4}, p;\n\t}"
        :: "r"(d), "l"(a), "l"(b), "r"(idesc), "r"(0u), "r"(en) : "memory");
}
__device__ __forceinline__ void tc_commit_mc_cg2(uint32_t mbar, uint16_t mask) {
    asm volatile(
        "tcgen05.commit.cta_group::2.mbarrier::arrive::one.shared::cluster"
        ".multicast::cluster.b64 [%0], %1;"
        :: "r"(mbar), "h"(mask) : "memory");
}
__device__ __forceinline__ void mbar_init(uint32_t mbar, uint32_t cnt) {
    asm volatile("mbarrier.init.shared.b64 [%0], %1;" :: "r"(mbar), "r"(cnt) : "memory");
}
__device__ __forceinline__ void mbar_expect_tx(uint32_t mbar, uint32_t bytes) {
    asm volatile("mbarrier.arrive.expect_tx.shared.b64 _, [%0], %1;"
                 :: "r"(mbar), "r"(bytes) : "memory");
}
__device__ __forceinline__ void mbar_arrive_leader(uint32_t mbar) {
    asm volatile(
        "{\n\t.reg .b32 la;\n\tand.b32 la, %0, 0xFEFFFFFF;\n\t"
        "mbarrier.arrive.shared::cluster.b64 _, [la];\n\t}"
        :: "r"(mbar) : "memory");
}
__device__ __forceinline__ void mbar_wait(uint32_t mbar, uint32_t parity) {
    uint32_t done;
    asm volatile(
        "{\n\t.reg .pred p;\n\t"
        "mbarrier.try_wait.parity.acquire.cta.shared::cta.b64 p, [%1], %2;\n\t"
        "selp.b32 %0, 1, 0, p;\n\t}"
        : "=r"(done) : "r"(mbar), "r"(parity) : "memory");
    if (!done) {
        asm volatile(
            "{\n\t.reg .pred P1;\n\t"
            "WAIT_LOOP_%=:\n\t"
            "mbarrier.try_wait.parity.acquire.cta.shared::cta.b64 P1, [%0], %1, 0x989680;\n\t"
            "@P1 bra.uni WAIT_DONE_%=;\n\t"
            "bra.uni WAIT_LOOP_%=;\n\t"
            "WAIT_DONE_%=:\n\t}"
            :: "r"(mbar), "r"(parity) : "memory");
    }
}
// cg2 TMA: both CTAs execute; complete_tx targets the PAIR LEADER's barrier.
__device__ __forceinline__ void tma_load_3d_cg2(uint32_t smem_addr, const void* map,
                                                int cx, int cy, int cz, uint32_t mbar) {
    asm volatile(
        "{\n\t.reg .b32 lb;\n\t"
        "and.b32 lb, %5, 0xFEFFFFFF;\n\t"
        "cp.async.bulk.tensor.3d.cta_group::2.shared::cluster.global"
        ".tile.mbarrier::complete_tx::bytes [%0], [%1, {%2, %3, %4}], [lb];\n\t}"
        :: "r"(smem_addr), "l"(map), "r"(cx), "r"(cy), "r"(cz), "r"(mbar) : "memory");
}
__device__ __forceinline__ void fence_proxy_async_cta() {
    asm volatile("fence.proxy.async.shared::cta;" ::: "memory");
}
__device__ __forceinline__ void cluster_sync() {
    asm volatile("barrier.cluster.arrive.aligned;" ::: "memory");
    asm volatile("barrier.cluster.wait.aligned;" ::: "memory");
}
__device__ __forceinline__ uint32_t ctarank() {
    uint32_t r; asm("mov.u32 %0, %%cluster_ctarank;" : "=r"(r)); return r;
}
__device__ __forceinline__ void tc_fence_after() {
    asm volatile("tcgen05.fence::after_thread_sync;" ::: "memory");
}
__device__ __forceinline__ void tc_fence_before() {
    asm volatile("tcgen05.fence::before_thread_sync;" ::: "memory");
}
__device__ __forceinline__ void tc_wait_ld() {
    asm volatile("tcgen05.wait::ld.sync.aligned;" ::: "memory");
}
__device__ __forceinline__ void ldtm_x32(uint32_t* r, uint32_t tmem_addr) {
    asm volatile(
        "tcgen05.ld.sync.aligned.32x32b.x32.b32 "
        "{%0, %1, %2, %3, %4, %5, %6, %7, "
        " %8, %9, %10, %11, %12, %13, %14, %15, "
        " %16, %17, %18, %19, %20, %21, %22, %23, "
        " %24, %25, %26, %27, %28, %29, %30, %31}, [%32];"
        : "=r"(r[0]),  "=r"(r[1]),  "=r"(r[2]),  "=r"(r[3]),
          "=r"(r[4]),  "=r"(r[5]),  "=r"(r[6]),  "=r"(r[7]),
          "=r"(r[8]),  "=r"(r[9]),  "=r"(r[10]), "=r"(r[11]),
          "=r"(r[12]), "=r"(r[13]), "=r"(r[14]), "=r"(r[15]),
          "=r"(r[16]), "=r"(r[17]), "=r"(r[18]), "=r"(r[19]),
          "=r"(r[20]), "=r"(r[21]), "=r"(r[22]), "=r"(r[23]),
          "=r"(r[24]), "=r"(r[25]), "=r"(r[26]), "=r"(r[27]),
          "=r"(r[28]), "=r"(r[29]), "=r"(r[30]), "=r"(r[31])
        : "r"(tmem_addr));
}
#endif  // HAS_TC

// ---------------- 1) LoRA hidden H = x @ lora_a AND x -> bf16 ---------------
// 128 threads: 4 warps x 4 rows = 16 rows/block -> 512 blocks. Lower register
// footprint (acc[4][8]) -> more resident blocks -> more loads in flight.
__global__ void __launch_bounds__(128) k_lora_conv(
    const float* __restrict__ x, const float* __restrict__ la) {
    using namespace cfg;
    const int warp = threadIdx.x >> 5, lane = threadIdx.x & 31;
    const int m0 = blockIdx.x * 16 + warp * 4;
    float acc[4][8];
#pragma unroll
    for (int i = 0; i < 4; i++)
#pragma unroll
        for (int j = 0; j < 8; j++) acc[i][j] = 0.0f;

    for (int it = 0; it < K / 128; it++) {
        const int k = it * 128 + lane * 4;
        const float4* lap = reinterpret_cast<const float4*>(la + (size_t)k * 8);
        float4 a[8];
#pragma unroll
        for (int j = 0; j < 8; j++) a[j] = lap[j];
#pragma unroll
        for (int rr = 0; rr < 4; rr++) {
            const size_t off = (size_t)(m0 + rr) * K + k;
            float4 xv = *reinterpret_cast<const float4*>(x + off);
            __nv_bfloat162 b0 = __floats2bfloat162_rn(xv.x, xv.y);
            __nv_bfloat162 b1 = __floats2bfloat162_rn(xv.z, xv.w);
            uint2 pk;
            pk.x = *reinterpret_cast<uint32_t*>(&b0);
            pk.y = *reinterpret_cast<uint32_t*>(&b1);
            *reinterpret_cast<uint2*>(g_X + off) = pk;
            acc[rr][0] += xv.x * a[0].x + xv.y * a[2].x + xv.z * a[4].x + xv.w * a[6].x;
            acc[rr][1] += xv.x * a[0].y + xv.y * a[2].y + xv.z * a[4].y + xv.w * a[6].y;
            acc[rr][2] += xv.x * a[0].z + xv.y * a[2].z + xv.z * a[4].z + xv.w * a[6].z;
            acc[rr][3] += xv.x * a[0].w + xv.y * a[2].w + xv.z * a[4].w + xv.w * a[6].w;
            acc[rr][4] += xv.x * a[1].x + xv.y * a[3].x + xv.z * a[5].x + xv.w * a[7].x;
            acc[rr][5] += xv.x * a[1].y + xv.y * a[3].y + xv.z * a[5].y + xv.w * a[7].y;
            acc[rr][6] += xv.x * a[1].z + xv.y * a[3].z + xv.z * a[5].z + xv.w * a[7].z;
            acc[rr][7] += xv.x * a[1].w + xv.y * a[3].w + xv.z * a[5].w + xv.w * a[7].w;
        }
    }
#pragma unroll
    for (int rr = 0; rr < 4; rr++)
#pragma unroll
        for (int r = 0; r < 8; r++) {
            float v = acc[rr][r];
#pragma unroll
            for (int off = 16; off; off >>= 1)
                v += __shfl_xor_sync(0xffffffffu, v, off);
            if (lane == 0) g_H[(m0 + rr) * 8 + r] = v;
        }
}

// ---------------- 2) NF4 dequant + transpose: g_Wt[n][k] (inline detect) -----
// Scale is per-block constant in k (64-row tile lies inside one 128-group),
// so it's loaded ONCE; the 4 q-loads are fully unrolled (front-batched MLP).
__global__ void __launch_bounds__(256) k_dequant_t(
    const int* __restrict__ q, const float* __restrict__ scale) {
    using namespace cfg;
    __shared__ __nv_bfloat16 t[64][66];     // 66-el pad: <=2-way read conflicts
    __shared__ int s_is32;
    const int k0 = blockIdx.y * 64;
    const int n0 = blockIdx.x * 64;
    const int tid = threadIdx.x;

    // Inline encoding detection: int32-per-code data has EVERY word with
    // (uint)(w+8)<16; packed int8 passes with p~2e-4 per word.
    if (tid < 32) {
        int4 w = reinterpret_cast<const int4*>(q)[tid];
        bool ok = ((unsigned)(w.x + 8) < 16u) && ((unsigned)(w.y + 8) < 16u) &&
                  ((unsigned)(w.z + 8) < 16u) && ((unsigned)(w.w + 8) < 16u);
        unsigned b = __ballot_sync(0xffffffffu, ok);
        if (tid == 0) s_is32 = (b == 0xffffffffu);
    }
    __syncthreads();
    const bool is32 = (s_is32 != 0);

    if (is32) {
        const int n4 = tid & 15;
        const int kb = tid >> 4;              // 0..15
        // scale group is constant over k0..k0+63
        float4 s = *reinterpret_cast<const float4*>(
            scale + (size_t)(k0 >> 7) * N + n0 + n4 * 4);
        int4 c[4];
#pragma unroll
        for (int it = 0; it < 4; it++) {
            int kk = kb + it * 16;
            c[it] = *(reinterpret_cast<const int4*>(q + (size_t)(k0 + kk) * N + n0) + n4);
        }
#pragma unroll
        for (int it = 0; it < 4; it++) {
            int kk = kb + it * 16;
            t[kk][n4 * 4 + 0] = __hmul(__float2bfloat16(c_nf4[c[it].x + 8]), __float2bfloat16(s.x));
            t[kk][n4 * 4 + 1] = __hmul(__float2bfloat16(c_nf4[c[it].y + 8]), __float2bfloat16(s.y));
            t[kk][n4 * 4 + 2] = __hmul(__float2bfloat16(c_nf4[c[it].z + 8]), __float2bfloat16(s.z));
            t[kk][n4 * 4 + 3] = __hmul(__float2bfloat16(c_nf4[c[it].w + 8]), __float2bfloat16(s.w));
        }
    } else {
        for (int idx = tid; idx < 64 * 64; idx += 256) {
            int kk = idx >> 6, nn = idx & 63;
            int code = (int)((const signed char*)q)[(size_t)(k0 + kk) * N + n0 + nn] + 8;
            float s = scale[(size_t)((k0 + kk) >> 7) * N + n0 + nn];
            t[kk][nn] = __hmul(__float2bfloat16(c_nf4[code]), __float2bfloat16(s));
        }
    }
    __syncthreads();
    // 64 n-rows x 8 k-groups of 8 = 512 uint4 stores over 256 threads (2 iters)
#pragma unroll
    for (int it = 0; it < 2; it++) {
        int idx = tid + it * 256;
        int nn = idx >> 3, kg = idx & 7;
        __nv_bfloat162 p[4];
#pragma unroll
        for (int i = 0; i < 4; i++)
            p[i] = __halves2bfloat162(t[kg * 8 + 2 * i][nn], t[kg * 8 + 2 * i + 1][nn]);
        uint4 v;
        v.x = *reinterpret_cast<uint32_t*>(&p[0]);
        v.y = *reinterpret_cast<uint32_t*>(&p[1]);
        v.z = *reinterpret_cast<uint32_t*>(&p[2]);
        v.w = *reinterpret_cast<uint32_t*>(&p[3]);
        *reinterpret_cast<uint4*>(g_Wt + (size_t)(n0 + nn) * K + k0 + kg * 8) = v;
    }
}

// ---------------- 3) main GEMM: persistent cg2 pairs, double-buffered TMEM --
__global__ void __launch_bounds__(cfg::NTHREADS, 1) __cluster_dims__(2, 1, 1) k_gemm(
    const __grid_constant__ CUtensorMap tma_a,    // g_X,  box {64,128,1}
    const __grid_constant__ CUtensorMap tma_b,    // g_Wt, box {64,128,1}
    const float* __restrict__ bias,
    const float* __restrict__ lb,      // lora_b [8][N]
    float* __restrict__ out) {
    using namespace cfg;
    extern __shared__ __align__(1024) char smem[];
    const uint32_t sbase = smem_u32(smem);
    const int tid  = threadIdx.x;
    const int warp = tid >> 5, lane = tid & 31;
    const int pair = blockIdx.y;

#if HAS_TC
    const uint32_t rank = ctarank();
    const uint16_t MASK = 0x3;

    if (warp == 8) {
        asm volatile("tcgen05.alloc.cta_group::2.sync.aligned.shared::cta.b32 [%0], %1;"
                     :: "r"(sbase), "r"(512u) : "memory");
        asm volatile("tcgen05.relinquish_alloc_permit.cta_group::2.sync.aligned;");
    }
    if (tid == 0) {
#pragma unroll
        for (int s = 0; s < STAGES; s++) {
            mbar_init(sbase + MBAR_FULL + s * 8, 1);
            mbar_init(sbase + MBAR_DONE + s * 8, 1);
        }
        mbar_init(sbase + MBAR_FIN + 0, 1);
        mbar_init(sbase + MBAR_FIN + 8, 1);
        mbar_init(sbase + MBAR_EPI + 0, 2);
        mbar_init(sbase + MBAR_EPI + 8, 2);
        fence_proxy_async_cta();
    }
    __syncthreads();
    cluster_sync();
    uint32_t tmem_base;
    asm volatile("ld.shared.b32 %0, [%1];" : "=r"(tmem_base) : "r"(sbase));

    if (tid == 288) {
        // ---------------- producer: continuous TMA ring across tiles --------
        int st = 0, ph = 0, g = 0;
        for (int ti = pair; ti < NTILES; ti += NPAIRS) {
            const int bm0 = (ti >> 4) * 256;
            const int bn0 = (ti & 15) * 256;
            for (int kt = 0; kt < NK; kt++) {
                if (g >= STAGES)
                    mbar_wait(sbase + MBAR_DONE + st * 8, ph ^ 1);
                uint32_t fullb = sbase + MBAR_FULL + st * 8;
                if (rank == 0)
                    mbar_expect_tx(fullb, (uint32_t)(2 * STAGE_BYTES));
                uint32_t s0 = sbase + SMEM_TILE + st * STAGE_BYTES;
                tma_load_3d_cg2(s0, &tma_a, kt * BK, bm0 + (int)rank * 128, 0, fullb);
                tma_load_3d_cg2(s0 + A_SLICE, &tma_b, kt * BK, bn0 + (int)rank * 128, 0, fullb);
                g++;
                if (++st == STAGES) { st = 0; ph ^= 1; }
            }
        }
    }
    if (rank == 0 && tid == 256) {
        // ---------------- consumer: MMA dispatch, double-buffered D ---------
        int st = 0, ph = 0;
        int tile_i = 0;
        for (int ti = pair; ti < NTILES; ti += NPAIRS, tile_i++) {
            const int buf = tile_i & 1;
            if (tile_i >= 2)
                mbar_wait(sbase + MBAR_EPI + buf * 8, ((tile_i - 2) >> 1) & 1);
            const uint32_t dbase = tmem_base + (uint32_t)buf * 256u;
            for (int kt = 0; kt < NK; kt++) {
                mbar_wait(sbase + MBAR_FULL + st * 8, ph);
                uint32_t s0 = sbase + SMEM_TILE + st * STAGE_BYTES;
                uint64_t ad = make_desc(s0);
                uint64_t bd = make_desc(s0 + A_SLICE);
#pragma unroll
                for (int ks = 0; ks < 4; ks++) {
                    uint32_t en = (kt > 0 || ks > 0) ? 1u : 0u;
                    mma_f16_ss_cg2(dbase, ad + ks * 2, bd + ks * 2, IDESC, en);
                }
                tc_commit_mc_cg2(sbase + MBAR_DONE + st * 8, MASK);
                if (++st == STAGES) { st = 0; ph ^= 1; }
            }
            tc_commit_mc_cg2(sbase + MBAR_FIN + buf * 8, MASK);
        }
    }
    if (tid < 256) {
        // ---------------- epilogue: drain buffer t while t+1 computes -------
        const int rg = warp & 3;           // TMEM subpartition (row group)
        const int ch = warp >> 2;          // column half (128 cols each)
        float* sc = reinterpret_cast<float*>(smem + SMEM_EPI) + warp * (32 * 33);
        float* st = reinterpret_cast<float*>(smem + SMEM_LBS) + warp * 288;
        int tile_i = 0;
        for (int ti = pair; ti < NTILES; ti += NPAIRS, tile_i++) {
            const int buf = tile_i & 1;
            const int bm0 = (ti >> 4) * 256;
            const int bn0 = (ti & 15) * 256;
            mbar_wait(sbase + MBAR_FIN + buf * 8, (tile_i >> 1) & 1);
            tc_fence_after();

            const int mrow = bm0 + (int)rank * 128 + rg * 32;
            const int m = mrow + lane;
            float4 ha = *reinterpret_cast<const float4*>(g_H + m * 8);
            float4 hb = *reinterpret_cast<const float4*>(g_H + m * 8 + 4);
            float h[8] = {ha.x, ha.y, ha.z, ha.w, hb.x, hb.y, hb.z, hb.w};
            const uint32_t dbase = tmem_base + (uint32_t)buf * 256u + ch * 128;

#pragma unroll
            for (int chunk = 0; chunk < 4; chunk++) {
                const int c0 = chunk * 32;
                uint32_t d[32];
                ldtm_x32(d, dbase + c0);
                const int n_base = bn0 + ch * 128 + c0;
                // stage lb + bias for this 32-column chunk (LDS broadcasts after)
                {
                    const int n = n_base + lane;
#pragma unroll
                    for (int rr = 0; rr < 8; rr++) st[rr * 32 + lane] = lb[rr * N + n];
                    st[256 + lane] = bias[n];
                }
                tc_wait_ld();
                __syncwarp();
#pragma unroll
                for (int r = 0; r < 32; r++) {
                    float delta = 0.0f;
#pragma unroll
                    for (int rr = 0; rr < 8; rr++) delta += h[rr] * st[rr * 32 + r];
                    __nv_bfloat16 bsum = __hadd(__float2bfloat16(__uint_as_float(d[r])),
                                                __float2bfloat16(st[256 + r]));
                    sc[lane * 33 + r] = __bfloat162float(bsum) + 2.0f * delta;
                }
                __syncwarp();
#pragma unroll
                for (int r = 0; r < 32; r++) {
                    out[(size_t)(mrow + r) * N + n_base + lane] = sc[r * 33 + lane];
                }
                __syncwarp();
            }
            tc_fence_before();
            asm volatile("bar.sync 1, 256;" ::: "memory");   // all 8 epi warps done
            if (tid == 0) mbar_arrive_leader(sbase + MBAR_EPI + buf * 8);
        }
    }
    __syncthreads();
    if (warp == 8) {
        asm volatile("tcgen05.dealloc.cta_group::2.sync.aligned.b32 %0, %1;"
                     :: "r"(tmem_base), "r"(512u));
    }
    cluster_sync();   // no CTA exits while peer cg2 traffic could be in flight

#else
    // ================= mma.sync fallback (compute_103 PTX pass only) =======
    (void)tma_a; (void)tma_b;
    constexpr int FB_A = 16384, FB_STAGE = 49152;
    uint32_t swoff[8], goff[8];
#pragma unroll
    for (int i = 0; i < 8; i++) {
        int c = (tid & 255) + i * 256;
        int row = c >> 3, col = c & 7;
        swoff[i] = sw128(row * 128 + col * 16);
        goff[i]  = (uint32_t)row * (K * 2) + col * 16;
    }
    const int wm = warp >> 2;
    const int wn = warp & 3;
    const int rankf = blockIdx.x & 1;

    for (int ti = pair; ti < NTILES; ti += NPAIRS) {
        const int bm0f = (ti >> 4) * 256 + rankf * 128;
        const int bn0  = (ti & 15) * 256;

        auto fb_loads = [&](int kt, int stg) {
            const char* gA = reinterpret_cast<const char*>(g_X)
                + (size_t)bm0f * (K * 2) + (size_t)kt * (BK * 2);
            const char* gB = reinterpret_cast<const char*>(g_Wt)
                + (size_t)bn0 * (K * 2) + (size_t)kt * (BK * 2);
            uint32_t sA = sbase + SMEM_TILE + stg * FB_STAGE;
            uint32_t sB = sA + FB_A;
#pragma unroll
        for (int i = 0; i < 4; i++) cp_async16(sA + swoff[i], gA + goff[i]);
#pragma unroll
        for (int i = 0; i < 8; i++) cp_async16(sB + swoff[i], gB + goff[i]);
        };

        float acc[4][8][4];
#pragma unroll
        for (int i = 0; i < 4; i++)
#pragma unroll
            for (int j = 0; j < 8; j++)
#pragma unroll
                for (int e = 0; e < 4; e++) acc[i][j][e] = 0.0f;

        if (tid < 256) { fb_loads(0, 0); }
        cp_commit();
        if (tid < 256) { fb_loads(1, 1); }
        cp_commit();

        for (int kt = 0; kt < NK; kt++) {
            const int stg = kt % 3;
            cp_wait<1>();
            __syncthreads();
            const int kn = kt + 2;
            if (kn < NK && tid < 256) fb_loads(kn, kn % 3);
            cp_commit();

            if (tid < 256) {
                const uint32_t aST = sbase + SMEM_TILE + stg * FB_STAGE;
                const uint32_t bST = aST + FB_A;
#pragma unroll
                for (int ks = 0; ks < 4; ks++) {
                    uint32_t afrag[4][4], bfrag[4][4];
#pragma unroll
                    for (int mt = 0; mt < 4; mt++) {
                        int row = wm * 64 + mt * 16 + (lane & 15);
                        ldsm_x4(afrag[mt], aST + sw128(row * 128 + ks * 32 + (lane >> 4) * 16));
                    }
#pragma unroll
                    for (int nt = 0; nt < 4; nt++) {
                        int row = wn * 64 + nt * 16 + (lane & 15);
                        ldsm_x4(bfrag[nt], bST + sw128(row * 128 + ks * 32 + (lane >> 4) * 16));
                    }
#pragma unroll
                    for (int mt = 0; mt < 4; mt++)
#pragma unroll
                        for (int nt = 0; nt < 4; nt++) {
                            mma16816(acc[mt][2 * nt],     afrag[mt], bfrag[nt][0], bfrag[nt][2]);
                            mma16816(acc[mt][2 * nt + 1], afrag[mt], bfrag[nt][1], bfrag[nt][3]);
                        }
                }
            }
            __syncthreads();
        }

        if (tid < 256) {
            const int mrow = lane >> 2;
            const int ncol = (lane & 3) * 2;
#pragma unroll
            for (int mt = 0; mt < 4; mt++) {
                int m0 = bm0f + wm * 64 + mt * 16 + mrow;
                const float4* h0p = reinterpret_cast<const float4*>(g_H + m0 * 8);
                const float4* h1p = reinterpret_cast<const float4*>(g_H + (m0 + 8) * 8);
                float4 h0a = h0p[0], h0b = h0p[1];
                float4 h1a = h1p[0], h1b = h1p[1];
                float h0r[8] = {h0a.x, h0a.y, h0a.z, h0a.w, h0b.x, h0b.y, h0b.z, h0b.w};
                float h1r[8] = {h1a.x, h1a.y, h1a.z, h1a.w, h1b.x, h1b.y, h1b.z, h1b.w};
#pragma unroll
                for (int nt = 0; nt < 8; nt++) {
                    int n0 = bn0 + wn * 64 + nt * 8 + ncol;
                    float d00 = 0.f, d01 = 0.f, d10 = 0.f, d11 = 0.f;
#pragma unroll
                    for (int r = 0; r < 8; r++) {
                        float l0 = lb[r * N + n0];
                        float l1 = lb[r * N + n0 + 1];
                        d00 += h0r[r] * l0;  d01 += h0r[r] * l1;
                        d10 += h1r[r] * l0;  d11 += h1r[r] * l1;
                    }
                    __nv_bfloat16 bb0 = __float2bfloat16(bias[n0]);
                    __nv_bfloat16 bb1 = __float2bfloat16(bias[n0 + 1]);
                    float o00 = __bfloat162float(__hadd(__float2bfloat16(acc[mt][nt][0]), bb0)) + 2.0f * d00;
                    float o01 = __bfloat162float(__hadd(__float2bfloat16(acc[mt][nt][1]), bb1)) + 2.0f * d01;
                    float o10 = __bfloat162float(__hadd(__float2bfloat16(acc[mt][nt][2]), bb0)) + 2.0f * d10;
                    float o11 = __bfloat162float(__hadd(__float2bfloat16(acc[mt][nt][3]), bb1)) + 2.0f * d11;
                    *reinterpret_cast<float2*>(out + (size_t)m0 * N + n0)       = make_float2(o00, o01);
                    *reinterpret_cast<float2*>(out + (size_t)(m0 + 8) * N + n0) = make_float2(o10, o11);
                }
            }
        }
        __syncthreads();
    }
#endif
}

// ---------------- launch ----------------
typedef CUresult (*PFN_tmEnc)(CUtensorMap*, CUtensorMapDataType, cuuint32_t, void*,
                              const cuuint64_t*, const cuuint64_t*,
                              const cuuint32_t*, const cuuint32_t*,
                              CUtensorMapInterleave, CUtensorMapSwizzle,
                              CUtensorMapL2promotion, CUtensorMapFloatOOBfill);

static void encode_map3(PFN_tmEnc enc, CUtensorMap* m, void* base, uint64_t rows) {
    cuuint64_t dims[3]    = {(cuuint64_t)cfg::K, (cuuint64_t)rows, 1};
    cuuint64_t strides[2] = {(cuuint64_t)cfg::K * 2, (cuuint64_t)rows * cfg::K * 2};
    cuuint32_t box[3]     = {64, 128, 1};            // 64 bf16 = 128B = SW128 atom
    cuuint32_t estr[3]    = {1, 1, 1};
    enc(m, CU_TENSOR_MAP_DATA_TYPE_BFLOAT16, 3, base, dims, strides, box, estr,
        CU_TENSOR_MAP_INTERLEAVE_NONE, CU_TENSOR_MAP_SWIZZLE_128B,
        CU_TENSOR_MAP_L2_PROMOTION_L2_128B, CU_TENSOR_MAP_FLOAT_OOB_FILL_NONE);
}

extern "C" void kernel_launch(void* const* d_in, const int* in_sizes, int n_in,
                              void* d_out, int out_size) {
    using namespace cfg;
    const float* x = nullptr; const void* q = nullptr; const float* scale = nullptr;
    const float* bias = nullptr; const float* la = nullptr; const float* lb = nullptr;
    for (int i = 0; i < n_in; i++) {
        switch (in_sizes[i]) {
            case 33554432: x = (const float*)d_in[i]; break;        // 8192*4096
            case 16777216: q = d_in[i]; break;                      // 4096*4096
            case 135168:   scale = (const float*)d_in[i]; break;    // 33*4096
            case 4096:     bias = (const float*)d_in[i]; break;
            case 32768:                                             // lora_a then lora_b
                if (!la) la = (const float*)d_in[i];
                else     lb = (const float*)d_in[i];
                break;
            default: break;
        }
    }
    float* out = (float*)d_out;

    // TMA tensormaps (driver entry point; no -lcuda needed)
    void* fn = nullptr;
    cudaDriverEntryPointQueryResult qres;
    cudaGetDriverEntryPoint("cuTensorMapEncodeTiled", &fn, cudaEnableDefault, &qres);
    PFN_tmEnc enc = (PFN_tmEnc)fn;
    void *xsym = nullptr, *wsym = nullptr;
    cudaGetSymbolAddress(&xsym, g_X);
    cudaGetSymbolAddress(&wsym, g_Wt);
    CUtensorMap tma_a, tma_b;
    encode_map3(enc, &tma_a, xsym, M);
    encode_map3(enc, &tma_b, wsym, N);

    k_dequant_t<<<dim3(N / 64, K / 64), 256>>>((const int*)q, scale);
    k_lora_conv<<<M / 16, 128>>>(x, la);

    cudaFuncSetAttribute(k_gemm, cudaFuncAttributeMaxDynamicSharedMemorySize, SMEM_TOTAL);
    k_gemm<<<dim3(2, NPAIRS), NTHREADS, SMEM_TOTAL>>>(tma_a, tma_b, bias, lb, out);
}

// round 15
// speedup vs baseline: 1.0025x; 1.0025x over previous
#include <cuda_runtime.h>
#include <cuda.h>
#include <cuda_bf16.h>
#include <cstdint>

// Arch-feature gate: tcgen05/TMA path only in the sm_103a cubin pass. The
// compute_103 PTX pass compiles the mma.sync fallback (never executed).
#if defined(__CUDA_ARCH__) && defined(__CUDA_ARCH_HAS_FEATURE__)
#if __CUDA_ARCH_HAS_FEATURE__(SM103_ALL)
#define HAS_TC 1
#else
#define HAS_TC 0
#endif
#else
#define HAS_TC 0
#endif

// ---------------- problem dims (fixed by setup_inputs) ----------------
namespace cfg {
constexpr int M = 8192;     // B*S
constexpr int N = 4096;     // D_OUT
constexpr int K = 4096;     // D_IN
constexpr int BM = 256, BN = 256, BK = 64;       // per cg2 pair
constexpr int STAGES = 5;
constexpr int NK = K / BK;                       // 64
constexpr int NTJ = (M / (2 * BM)) * (N / BN);   // 256 tile-pairs (2 M-tiles share B)
constexpr int NGROUPS = 33;                      // 33 x 4-CTA clusters = 132 CTAs
constexpr int A_SLICE = 128 * BK * 2;            // 16384 (per-CTA A rows)
constexpr int B_SLICE = 128 * BK * 2;            // 16384 (per-CTA B rows, N/2)
constexpr int STAGE_BYTES = A_SLICE + B_SLICE;   // 32768
constexpr int SMEM_TILE = 1024;
constexpr int SMEM_EPI  = SMEM_TILE + STAGES * STAGE_BYTES;   // 164864
constexpr int SMEM_LBS  = SMEM_EPI + 8 * 32 * 33 * 4;         // 198656
constexpr int SMEM_TOTAL = SMEM_LBS + 8 * 288 * 4;            // 207872
constexpr int MBAR_FULL = 64;                    // 5 x 8B  (per-CTA A+B arrival)
constexpr int MBAR_DONE = 112;                   // 5 x 8B  (both pairs' commits)
constexpr int MBAR_PF   = 160;                   // 5 x 8B  (peer-full relay)
constexpr int MBAR_FIN  = 208;                   // 2 x 8B
constexpr int MBAR_EPI  = 224;                   // 2 x 8B
constexpr int NTHREADS = 320;                    // 8 epi warps + consumer/relay + producer
// cg2 idesc: M_TOTAL=256 x N=256 kind::f16 bf16
constexpr uint32_t IDESC = 0x10u | 0x80u | 0x400u | ((256 / 8) << 17) | ((256 / 16) << 24);
}

// ---------------- scratch ----------------
__device__ __nv_bfloat16 g_X [(size_t)cfg::M * cfg::K];   // x in bf16, [M][K]
__device__ __nv_bfloat16 g_Wt[(size_t)cfg::N * cfg::K];   // W^T bf16, [N][K] K-major
__device__ float         g_H [cfg::M * 8];                // LoRA hidden

__constant__ float c_nf4[16] = {
    -1.0f, -0.6962f, -0.5251f, -0.3949f, -0.2844f, -0.1848f, -0.0911f, 0.0f,
     0.0796f, 0.1609f, 0.2461f, 0.3379f, 0.4407f, 0.5626f, 0.723f, 1.0f};

// ---------------- generic helpers ----------------
__device__ __forceinline__ uint32_t smem_u32(const void* p) {
    return (uint32_t)__cvta_generic_to_shared(p);
}
__device__ __forceinline__ void cp_async16(uint32_t s, const void* g) {
    asm volatile("cp.async.cg.shared.global [%0], [%1], 16;" :: "r"(s), "l"(g));
}
__device__ __forceinline__ void cp_commit() { asm volatile("cp.async.commit_group;"); }
template <int W>
__device__ __forceinline__ void cp_wait() {
    asm volatile("cp.async.wait_group %0;" :: "n"(W));
}
__device__ __forceinline__ uint32_t sw128(uint32_t b) { return b ^ ((b >> 3) & 0x70); }

__device__ __forceinline__ void ldsm_x4(uint32_t a[4], uint32_t addr) {
    asm volatile("ldmatrix.sync.aligned.m8n8.x4.shared.b16 {%0,%1,%2,%3}, [%4];"
                 : "=r"(a[0]), "=r"(a[1]), "=r"(a[2]), "=r"(a[3]) : "r"(addr));
}
__device__ __forceinline__ void mma16816(float d[4], const uint32_t a[4],
                                         uint32_t b0, uint32_t b1) {
    asm volatile(
        "mma.sync.aligned.m16n8k16.row.col.f32.bf16.bf16.f32 "
        "{%0,%1,%2,%3}, {%4,%5,%6,%7}, {%8,%9}, {%0,%1,%2,%3};"
        : "+f"(d[0]), "+f"(d[1]), "+f"(d[2]), "+f"(d[3])
        : "r"(a[0]), "r"(a[1]), "r"(a[2]), "r"(a[3]), "r"(b0), "r"(b1));
}

#if HAS_TC
// ---------------- tcgen05/TMA helpers (sm_103a pass only) ----------------
__device__ __forceinline__ uint64_t make_desc(uint32_t addr) {
    constexpr uint64_t BASE =
        (uint64_t(2) << 61) | (uint64_t(1) << 46) | (uint64_t(64) << 32) | (uint64_t(1) << 16);
    return BASE | ((uint64_t)(addr >> 4) & 0x3FFF);
}
__device__ __forceinline__ void mma_f16_ss_cg2(uint32_t d, uint64_t a, uint64_t b,
                                               uint32_t idesc, uint32_t en) {
    asm volatile(
        "{\n\t.reg .pred p;\n\tsetp.ne.u32 p, %5, 0;\n\t"
        "tcgen05.mma.cta_group::2.kind::f16 [%0], %1, %2, %3, "
        "{%4, %4, %4, %4, %4, %4, %4, %4}, p;\n\t}"
        :: "r"(d), "l"(a), "l"(b), "r"(idesc), "r"(0u), "r"(en) : "memory");
}
__device__ __forceinline__ void tc_commit_mc_cg2(uint32_t mbar, uint16_t mask) {
    asm volatile(
        "tcgen05.commit.cta_group::2.mbarrier::arrive::one.shared::cluster"
        ".multicast::cluster.b64 [%0], %1;"
        :: "r"(mbar), "h"(mask) : "memory");
}
__device__ __forceinline__ void mbar_init(uint32_t mbar, uint32_t cnt) {
    asm volatile("mbarrier.init.shared.b64 [%0], %1;" :: "r"(mbar), "r"(cnt) : "memory");
}
__device__ __forceinline__ void mbar_expect_tx(uint32_t mbar, uint32_t bytes) {
    asm volatile("mbarrier.arrive.expect_tx.shared.b64 _, [%0], %1;"
                 :: "r"(mbar), "r"(bytes) : "memory");
}
__device__ __forceinline__ void mbar_arrive_leader(uint32_t mbar) {
    asm volatile(
        "{\n\t.reg .b32 la;\n\tand.b32 la, %0, 0xFEFFFFFF;\n\t"
        "mbarrier.arrive.shared::cluster.b64 _, [la];\n\t}"
        :: "r"(mbar) : "memory");
}
__device__ __forceinline__ void mbar_wait(uint32_t mbar, uint32_t parity) {
    uint32_t done;
    asm volatile(
        "{\n\t.reg .pred p;\n\t"
        "mbarrier.try_wait.parity.acquire.cta.shared::cta.b64 p, [%1], %2;\n\t"
        "selp.b32 %0, 1, 0, p;\n\t}"
        : "=r"(done) : "r"(mbar), "r"(parity) : "memory");
    if (!done) {
        asm volatile(
            "{\n\t.reg .pred P1;\n\t"
            "WAIT_LOOP_%=:\n\t"
            "mbarrier.try_wait.parity.acquire.cta.shared::cta.b64 P1, [%0], %1, 0x989680;\n\t"
            "@P1 bra.uni WAIT_DONE_%=;\n\t"
            "bra.uni WAIT_LOOP_%=;\n\t"
            "WAIT_DONE_%=:\n\t}"
            :: "r"(mbar), "r"(parity) : "memory");
    }
}
// regular per-CTA TMA: completion to this CTA's own barrier
__device__ __forceinline__ void tma_load_3d(uint32_t smem_addr, const void* map,
                                            int cx, int cy, int cz, uint32_t mbar) {
    asm volatile(
        "cp.async.bulk.tensor.3d.shared::cta.global.tile.mbarrier::complete_tx::bytes "
        "[%0], [%1, {%2, %3, %4}], [%5];"
        :: "r"(smem_addr), "l"(map), "r"(cx), "r"(cy), "r"(cz), "r"(mbar) : "memory");
}
// multicast TMA: data + complete_tx to the same smem offset in every masked CTA
__device__ __forceinline__ void tma_load_3d_mc(uint32_t smem_addr, const void* map,
                                               int cx, int cy, int cz, uint32_t mbar,
                                               uint16_t mask) {
    asm volatile(
        "cp.async.bulk.tensor.3d.shared::cluster.global.tile.mbarrier::complete_tx::bytes"
        ".multicast::cluster [%0], [%1, {%2, %3, %4}], [%5], %6;"
        :: "r"(smem_addr), "l"(map), "r"(cx), "r"(cy), "r"(cz), "r"(mbar), "h"(mask)
        : "memory");
}
__device__ __forceinline__ void fence_proxy_async_cta() {
    asm volatile("fence.proxy.async.shared::cta;" ::: "memory");
}
__device__ __forceinline__ void cluster_sync() {
    asm volatile("barrier.cluster.arrive.aligned;" ::: "memory");
    asm volatile("barrier.cluster.wait.aligned;" ::: "memory");
}
__device__ __forceinline__ uint32_t ctarank() {
    uint32_t r; asm("mov.u32 %0, %%cluster_ctarank;" : "=r"(r)); return r;
}
__device__ __forceinline__ void tc_fence_after() {
    asm volatile("tcgen05.fence::after_thread_sync;" ::: "memory");
}
__device__ __forceinline__ void tc_fence_before() {
    asm volatile("tcgen05.fence::before_thread_sync;" ::: "memory");
}
__device__ __forceinline__ void tc_wait_ld() {
    asm volatile("tcgen05.wait::ld.sync.aligned;" ::: "memory");
}
__device__ __forceinline__ void ldtm_x32(uint32_t* r, uint32_t tmem_addr) {
    asm volatile(
        "tcgen05.ld.sync.aligned.32x32b.x32.b32 "
        "{%0, %1, %2, %3, %4, %5, %6, %7, "
        " %8, %9, %10, %11, %12, %13, %14, %15, "
        " %16, %17, %18, %19, %20, %21, %22, %23, "
        " %24, %25, %26, %27, %28, %29, %30, %31}, [%32];"
        : "=r"(r[0]),  "=r"(r[1]),  "=r"(r[2]),  "=r"(r[3]),
          "=r"(r[4]),  "=r"(r[5]),  "=r"(r[6]),  "=r"(r[7]),
          "=r"(r[8]),  "=r"(r[9]),  "=r"(r[10]), "=r"(r[11]),
          "=r"(r[12]), "=r"(r[13]), "=r"(r[14]), "=r"(r[15]),
          "=r"(r[16]), "=r"(r[17]), "=r"(r[18]), "=r"(r[19]),
          "=r"(r[20]), "=r"(r[21]), "=r"(r[22]), "=r"(r[23]),
          "=r"(r[24]), "=r"(r[25]), "=r"(r[26]), "=r"(r[27]),
          "=r"(r[28]), "=r"(r[29]), "=r"(r[30]), "=r"(r[31])
        : "r"(tmem_addr));
}
#endif  // HAS_TC

// ---------------- 1) LoRA hidden H = x @ lora_a AND x -> bf16 (R13 best) ----
__global__ void __launch_bounds__(128) k_lora_conv(
    const float* __restrict__ x, const float* __restrict__ la) {
    using namespace cfg;
    const int warp = threadIdx.x >> 5, lane = threadIdx.x & 31;
    const int m0 = blockIdx.x * 32 + warp * 8;
    float acc[8][8];
#pragma unroll
    for (int i = 0; i < 8; i++)
#pragma unroll
        for (int j = 0; j < 8; j++) acc[i][j] = 0.0f;

    for (int it = 0; it < K / 128; it++) {
        const int k = it * 128 + lane * 4;
        const float4* lap = reinterpret_cast<const float4*>(la + (size_t)k * 8);
        float4 a[8];
#pragma unroll
        for (int j = 0; j < 8; j++) a[j] = lap[j];
#pragma unroll
        for (int rr = 0; rr < 8; rr++) {
            const size_t off = (size_t)(m0 + rr) * K + k;
            float4 xv = *reinterpret_cast<const float4*>(x + off);
            __nv_bfloat162 b0 = __floats2bfloat162_rn(xv.x, xv.y);
            __nv_bfloat162 b1 = __floats2bfloat162_rn(xv.z, xv.w);
            uint2 pk;
            pk.x = *reinterpret_cast<uint32_t*>(&b0);
            pk.y = *reinterpret_cast<uint32_t*>(&b1);
            *reinterpret_cast<uint2*>(g_X + off) = pk;
            acc[rr][0] += xv.x * a[0].x + xv.y * a[2].x + xv.z * a[4].x + xv.w * a[6].x;
            acc[rr][1] += xv.x * a[0].y + xv.y * a[2].y + xv.z * a[4].y + xv.w * a[6].y;
            acc[rr][2] += xv.x * a[0].z + xv.y * a[2].z + xv.z * a[4].z + xv.w * a[6].z;
            acc[rr][3] += xv.x * a[0].w + xv.y * a[2].w + xv.z * a[4].w + xv.w * a[6].w;
            acc[rr][4] += xv.x * a[1].x + xv.y * a[3].x + xv.z * a[5].x + xv.w * a[7].x;
            acc[rr][5] += xv.x * a[1].y + xv.y * a[3].y + xv.z * a[5].y + xv.w * a[7].y;
            acc[rr][6] += xv.x * a[1].z + xv.y * a[3].z + xv.z * a[5].z + xv.w * a[7].z;
            acc[rr][7] += xv.x * a[1].w + xv.y * a[3].w + xv.z * a[5].w + xv.w * a[7].w;
        }
    }
#pragma unroll
    for (int rr = 0; rr < 8; rr++)
#pragma unroll
        for (int r = 0; r < 8; r++) {
            float v = acc[rr][r];
#pragma unroll
            for (int off = 16; off; off >>= 1)
                v += __shfl_xor_sync(0xffffffffu, v, off);
            if (lane == 0) g_H[(m0 + rr) * 8 + r] = v;
        }
}

// ---------------- 2) NF4 dequant + transpose: g_Wt[n][k] (R13 best) ----------
__global__ void __launch_bounds__(256) k_dequant_t(
    const int* __restrict__ q, const float* __restrict__ scale) {
    using namespace cfg;
    __shared__ __nv_bfloat16 t[64][66];
    __shared__ int s_is32;
    const int k0 = blockIdx.y * 64;
    const int n0 = blockIdx.x * 64;
    const int tid = threadIdx.x;

    if (tid < 32) {
        int4 w = reinterpret_cast<const int4*>(q)[tid];
        bool ok = ((unsigned)(w.x + 8) < 16u) && ((unsigned)(w.y + 8) < 16u) &&
                  ((unsigned)(w.z + 8) < 16u) && ((unsigned)(w.w + 8) < 16u);
        unsigned b = __ballot_sync(0xffffffffu, ok);
        if (tid == 0) s_is32 = (b == 0xffffffffu);
    }
    __syncthreads();
    const bool is32 = (s_is32 != 0);

    if (is32) {
        for (int idx = tid; idx < 64 * 16; idx += 256) {
            int kk = idx >> 4, n4 = idx & 15;
            const size_t row = (size_t)(k0 + kk) * N + n0;
            int4 c = *(reinterpret_cast<const int4*>(q + row) + n4);
            float4 s = *reinterpret_cast<const float4*>(
                scale + (size_t)((k0 + kk) >> 7) * N + n0 + n4 * 4);
            t[kk][n4 * 4 + 0] = __hmul(__float2bfloat16(c_nf4[c.x + 8]), __float2bfloat16(s.x));
            t[kk][n4 * 4 + 1] = __hmul(__float2bfloat16(c_nf4[c.y + 8]), __float2bfloat16(s.y));
            t[kk][n4 * 4 + 2] = __hmul(__float2bfloat16(c_nf4[c.z + 8]), __float2bfloat16(s.z));
            t[kk][n4 * 4 + 3] = __hmul(__float2bfloat16(c_nf4[c.w + 8]), __float2bfloat16(s.w));
        }
    } else {
        for (int idx = tid; idx < 64 * 64; idx += 256) {
            int kk = idx >> 6, nn = idx & 63;
            int code = (int)((const signed char*)q)[(size_t)(k0 + kk) * N + n0 + nn] + 8;
            float s = scale[(size_t)((k0 + kk) >> 7) * N + n0 + nn];
            t[kk][nn] = __hmul(__float2bfloat16(c_nf4[code]), __float2bfloat16(s));
        }
    }
    __syncthreads();
#pragma unroll
    for (int it = 0; it < 2; it++) {
        int idx = tid + it * 256;
        int nn = idx >> 3, kg = idx & 7;
        __nv_bfloat162 p[4];
#pragma unroll
        for (int i = 0; i < 4; i++)
            p[i] = __halves2bfloat162(t[kg * 8 + 2 * i][nn], t[kg * 8 + 2 * i + 1][nn]);
        uint4 v;
        v.x = *reinterpret_cast<uint32_t*>(&p[0]);
        v.y = *reinterpret_cast<uint32_t*>(&p[1]);
        v.z = *reinterpret_cast<uint32_t*>(&p[2]);
        v.w = *reinterpret_cast<uint32_t*>(&p[3]);
        *reinterpret_cast<uint4*>(g_Wt + (size_t)(n0 + nn) * K + k0 + kg * 8) = v;
    }
}

// ---------------- 3) main GEMM: persistent 4-CTA clusters -------------------
// Cluster of 4 = two cg2 pairs {0,1},{2,3} computing two M-adjacent 256x256
// tiles that SHARE the B tile. B halves delivered by TMA multicast between
// non-paired CTAs ({0,2}: rows [bn,+128); {1,3}: rows [bn+128,+256)), halving
// B traffic chip-wide. Per-CTA full barriers; odd ranks relay "full" to their
// pair leader; done[st] counts both pairs' commits (B buffers shared).
__global__ void __launch_bounds__(cfg::NTHREADS, 1) __cluster_dims__(4, 1, 1) k_gemm(
    const __grid_constant__ CUtensorMap tma_a,    // g_X,  box {64,128,1}
    const __grid_constant__ CUtensorMap tma_b,    // g_Wt, box {64,128,1}
    const float* __restrict__ bias,
    const float* __restrict__ lb,      // lora_b [8][N]
    float* __restrict__ out) {
    using namespace cfg;
    extern __shared__ __align__(1024) char smem[];
    const uint32_t sbase = smem_u32(smem);
    const int tid  = threadIdx.x;
    const int warp = tid >> 5, lane = tid & 31;
    const int group = blockIdx.y;

#if HAS_TC
    const uint32_t rank = ctarank();              // 0..3
    const int pairid = (int)(rank >> 1);          // which cg2 pair
    const int prank  = (int)(rank & 1);           // rank within pair

    if (warp == 8) {
        asm volatile("tcgen05.alloc.cta_group::2.sync.aligned.shared::cta.b32 [%0], %1;"
                     :: "r"(sbase), "r"(512u) : "memory");
        asm volatile("tcgen05.relinquish_alloc_permit.cta_group::2.sync.aligned;");
    }
    if (tid == 0) {
#pragma unroll
        for (int s = 0; s < STAGES; s++) {
            mbar_init(sbase + MBAR_FULL + s * 8, 1);   // own expect_tx arrive
            mbar_init(sbase + MBAR_DONE + s * 8, 2);   // BOTH pairs' commits
            mbar_init(sbase + MBAR_PF   + s * 8, 1);   // peer-full relay
        }
        mbar_init(sbase + MBAR_FIN + 0, 1);
        mbar_init(sbase + MBAR_FIN + 8, 1);
        mbar_init(sbase + MBAR_EPI + 0, 2);            // pair's two epilogues
        mbar_init(sbase + MBAR_EPI + 8, 2);
        fence_proxy_async_cta();
    }
    __syncthreads();
    cluster_sync();
    uint32_t tmem_base;
    asm volatile("ld.shared.b32 %0, [%1];" : "=r"(tmem_base) : "r"(sbase));

    if (tid == 288) {
        // ---------------- producer: per-CTA A TMA + (ranks 0,1) B multicast -
        const uint16_t bmask = (rank == 0) ? 0x5 : 0xA;   // {0,2} / {1,3}
        int st = 0, ph = 0, g = 0;
        for (int tj = group; tj < NTJ; tj += NGROUPS) {
            const int mj = tj >> 4, ni = tj & 15;
            const int arow = (2 * mj + pairid) * 256 + prank * 128;
            const int bn0  = ni * 256;
            for (int kt = 0; kt < NK; kt++) {
                if (g >= STAGES)
                    mbar_wait(sbase + MBAR_DONE + st * 8, ph ^ 1);
                uint32_t fullb = sbase + MBAR_FULL + st * 8;
                mbar_expect_tx(fullb, (uint32_t)STAGE_BYTES);
                uint32_t s0 = sbase + SMEM_TILE + st * STAGE_BYTES;
                tma_load_3d(s0, &tma_a, kt * BK, arow, 0, fullb);
                if (rank < 2)
                    tma_load_3d_mc(s0 + A_SLICE, &tma_b, kt * BK,
                                   bn0 + (int)rank * 128, 0, fullb, bmask);
                g++;
                if (++st == STAGES) { st = 0; ph ^= 1; }
            }
        }
    }
    if (prank == 1 && tid == 256) {
        // ---------------- relay (odd ranks): forward full -> pair leader ----
        int st = 0, ph = 0;
        for (int tj = group; tj < NTJ; tj += NGROUPS) {
            for (int kt = 0; kt < NK; kt++) {
                mbar_wait(sbase + MBAR_FULL + st * 8, ph);
                mbar_arrive_leader(sbase + MBAR_PF + st * 8);
                if (++st == STAGES) { st = 0; ph ^= 1; }
            }
        }
    }
    if (prank == 0 && tid == 256) {
        // ---------------- consumer (pair leaders): MMA dispatch -------------
        const uint16_t pairmask = (uint16_t)(0x3 << (pairid * 2));
        int st = 0, ph = 0;
        int tile_i = 0;
        for (int tj = group; tj < NTJ; tj += NGROUPS, tile_i++) {
            const int buf = tile_i & 1;
            if (tile_i >= 2)
                mbar_wait(sbase + MBAR_EPI + buf * 8, ((tile_i - 2) >> 1) & 1);
            const uint32_t dbase = tmem_base + (uint32_t)buf * 256u;
            for (int kt = 0; kt < NK; kt++) {
                mbar_wait(sbase + MBAR_FULL + st * 8, ph);   // own A+B
                mbar_wait(sbase + MBAR_PF   + st * 8, ph);   // peer A+B
                uint32_t s0 = sbase + SMEM_TILE + st * STAGE_BYTES;
                uint64_t ad = make_desc(s0);
                uint64_t bd = make_desc(s0 + A_SLICE);
#pragma unroll
                for (int ks = 0; ks < 4; ks++) {
                    uint32_t en = (kt > 0 || ks > 0) ? 1u : 0u;
                    mma_f16_ss_cg2(dbase, ad + ks * 2, bd + ks * 2, IDESC, en);
                }
                tc_commit_mc_cg2(sbase + MBAR_DONE + st * 8, 0xF);  // all 4 CTAs
                if (++st == STAGES) { st = 0; ph ^= 1; }
            }
            tc_commit_mc_cg2(sbase + MBAR_FIN + buf * 8, pairmask);
        }
    }
    if (tid < 256) {
        // ---------------- epilogue: drain buffer t while t+1 computes -------
        const int rg = warp & 3;           // TMEM subpartition (row group)
        const int ch = warp >> 2;          // column half (128 cols each)
        float* sc = reinterpret_cast<float*>(smem + SMEM_EPI) + warp * (32 * 33);
        float* st = reinterpret_cast<float*>(smem + SMEM_LBS) + warp * 288;
        int tile_i = 0;
        for (int tj = group; tj < NTJ; tj += NGROUPS, tile_i++) {
            const int buf = tile_i & 1;
            const int mj = tj >> 4, ni = tj & 15;
            const int bn0 = ni * 256;
            mbar_wait(sbase + MBAR_FIN + buf * 8, (tile_i >> 1) & 1);
            tc_fence_after();

            const int mrow = (2 * mj + pairid) * 256 + prank * 128 + rg * 32;
            const int m = mrow + lane;
            float4 ha = *reinterpret_cast<const float4*>(g_H + m * 8);
            float4 hb = *reinterpret_cast<const float4*>(g_H + m * 8 + 4);
            float h[8] = {ha.x, ha.y, ha.z, ha.w, hb.x, hb.y, hb.z, hb.w};
            const uint32_t dbase = tmem_base + (uint32_t)buf * 256u + ch * 128;

#pragma unroll
            for (int chunk = 0; chunk < 4; chunk++) {
                const int c0 = chunk * 32;
                uint32_t d[32];
                ldtm_x32(d, dbase + c0);
                const int n_base = bn0 + ch * 128 + c0;
                {
                    const int n = n_base + lane;
#pragma unroll
                    for (int rr = 0; rr < 8; rr++) st[rr * 32 + lane] = lb[rr * N + n];
                    st[256 + lane] = bias[n];
                }
                tc_wait_ld();
                __syncwarp();
#pragma unroll
                for (int r = 0; r < 32; r++) {
                    float delta = 0.0f;
#pragma unroll
                    for (int rr = 0; rr < 8; rr++) delta += h[rr] * st[rr * 32 + r];
                    __nv_bfloat16 bsum = __hadd(__float2bfloat16(__uint_as_float(d[r])),
                                                __float2bfloat16(st[256 + r]));
                    sc[lane * 33 + r] = __bfloat162float(bsum) + 2.0f * delta;
                }
                __syncwarp();
#pragma unroll
                for (int r = 0; r < 32; r++) {
                    out[(size_t)(mrow + r) * N + n_base + lane] = sc[r * 33 + lane];
                }
                __syncwarp();
            }
            tc_fence_before();
            asm volatile("bar.sync 1, 256;" ::: "memory");   // all 8 epi warps done
            if (tid == 0) mbar_arrive_leader(sbase + MBAR_EPI + buf * 8);
        }
    }
    __syncthreads();
    if (warp == 8) {
        asm volatile("tcgen05.dealloc.cta_group::2.sync.aligned.b32 %0, %1;"
                     :: "r"(tmem_base), "r"(512u));
    }
    cluster_sync();   // no CTA exits while peer traffic could be in flight

#else
    // ================= mma.sync fallback (compute_103 PTX pass only) =======
    (void)tma_a; (void)tma_b;
    constexpr int FB_A = 16384, FB_STAGE = 49152;
    uint32_t swoff[8], goff[8];
#pragma unroll
    for (int i = 0; i < 8; i++) {
        int c = (tid & 255) + i * 256;
        int row = c >> 3, col = c & 7;
        swoff[i] = sw128(row * 128 + col * 16);
        goff[i]  = (uint32_t)row * (K * 2) + col * 16;
    }
    const int wm = warp >> 2;
    const int wn = warp & 3;
    const int rankf = blockIdx.x & 1;
    const int pidf  = (blockIdx.x >> 1) & 1;

    for (int tj = group; tj < NTJ; tj += NGROUPS) {
        const int mj = tj >> 4, ni = tj & 15;
        const int bm0f = (2 * mj + pidf) * 256 + rankf * 128;
        const int bn0  = ni * 256;

        auto fb_loads = [&](int kt, int stg) {
            const char* gA = reinterpret_cast<const char*>(g_X)
                + (size_t)bm0f * (K * 2) + (size_t)kt * (BK * 2);
            const char* gB = reinterpret_cast<const char*>(g_Wt)
                + (size_t)bn0 * (K * 2) + (size_t)kt * (BK * 2);
            uint32_t sA = sbase + SMEM_TILE + stg * FB_STAGE;
            uint32_t sB = sA + FB_A;
#pragma unroll
            for (int i = 0; i < 4; i++) cp_async16(sA + swoff[i], gA + goff[i]);
#pragma unroll
            for (int i = 0; i < 8; i++) cp_async16(sB + swoff[i], gB + goff[i]);
        };

        float acc[4][8][4];
#pragma unroll
        for (int i = 0; i < 4; i++)
#pragma unroll
            for (int j = 0; j < 8; j++)
#pragma unroll
                for (int e = 0; e < 4; e++) acc[i][j][e] = 0.0f;

        if (tid < 256) { fb_loads(0, 0); }
        cp_commit();
        if (tid < 256) { fb_loads(1, 1); }
        cp_commit();

        for (int kt = 0; kt < NK; kt++) {
            const int stg = kt % 3;
            cp_wait<1>();
            __syncthreads();
            const int kn = kt + 2;
            if (kn < NK && tid < 256) fb_loads(kn, kn % 3);
            cp_commit();

            if (tid < 256) {
                const uint32_t aST = sbase + SMEM_TILE + stg * FB_STAGE;
                const uint32_t bST = aST + FB_A;
#pragma unroll
                for (int ks = 0; ks < 4; ks++) {
                    uint32_t afrag[4][4], bfrag[4][4];
#pragma unroll
                    for (int mt = 0; mt < 4; mt++) {
                        int row = wm * 64 + mt * 16 + (lane & 15);
                        ldsm_x4(afrag[mt], aST + sw128(row * 128 + ks * 32 + (lane >> 4) * 16));
                    }
#pragma unroll
                    for (int nt = 0; nt < 4; nt++) {
                        int row = wn * 64 + nt * 16 + (lane & 15);
                        ldsm_x4(bfrag[nt], bST + sw128(row * 128 + ks * 32 + (lane >> 4) * 16));
                    }
#pragma unroll
                    for (int mt = 0; mt < 4; mt++)
#pragma unroll
                        for (int nt = 0; nt < 4; nt++) {
                            mma16816(acc[mt][2 * nt],     afrag[mt], bfrag[nt][0], bfrag[nt][2]);
                            mma16816(acc[mt][2 * nt + 1], afrag[mt], bfrag[nt][1], bfrag[nt][3]);
                        }
                }
            }
            __syncthreads();
        }

        if (tid < 256) {
            const int mrow = lane >> 2;
            const int ncol = (lane & 3) * 2;
#pragma unroll
            for (int mt = 0; mt < 4; mt++) {
                int m0 = bm0f + wm * 64 + mt * 16 + mrow;
                const float4* h0p = reinterpret_cast<const float4*>(g_H + m0 * 8);
                const float4* h1p = reinterpret_cast<const float4*>(g_H + (m0 + 8) * 8);
                float4 h0a = h0p[0], h0b = h0p[1];
                float4 h1a = h1p[0], h1b = h1p[1];
                float h0r[8] = {h0a.x, h0a.y, h0a.z, h0a.w, h0b.x, h0b.y, h0b.z, h0b.w};
                float h1r[8] = {h1a.x, h1a.y, h1a.z, h1a.w, h1b.x, h1b.y, h1b.z, h1b.w};
#pragma unroll
                for (int nt = 0; nt < 8; nt++) {
                    int n0 = bn0 + wn * 64 + nt * 8 + ncol;
                    float d00 = 0.f, d01 = 0.f, d10 = 0.f, d11 = 0.f;
#pragma unroll
                    for (int r = 0; r < 8; r++) {
                        float l0 = lb[r * N + n0];
                        float l1 = lb[r * N + n0 + 1];
                        d00 += h0r[r] * l0;  d01 += h0r[r] * l1;
                        d10 += h1r[r] * l0;  d11 += h1r[r] * l1;
                    }
                    __nv_bfloat16 bb0 = __float2bfloat16(bias[n0]);
                    __nv_bfloat16 bb1 = __float2bfloat16(bias[n0 + 1]);
                    float o00 = __bfloat162float(__hadd(__float2bfloat16(acc[mt][nt][0]), bb0)) + 2.0f * d00;
                    float o01 = __bfloat162float(__hadd(__float2bfloat16(acc[mt][nt][1]), bb1)) + 2.0f * d01;
                    float o10 = __bfloat162float(__hadd(__float2bfloat16(acc[mt][nt][2]), bb0)) + 2.0f * d10;
                    float o11 = __bfloat162float(__hadd(__float2bfloat16(acc[mt][nt][3]), bb1)) + 2.0f * d11;
                    *reinterpret_cast<float2*>(out + (size_t)m0 * N + n0)       = make_float2(o00, o01);
                    *reinterpret_cast<float2*>(out + (size_t)(m0 + 8) * N + n0) = make_float2(o10, o11);
                }
            }
        }
        __syncthreads();
    }
#endif
}

// ---------------- launch ----------------
typedef CUresult (*PFN_tmEnc)(CUtensorMap*, CUtensorMapDataType, cuuint32_t, void*,
                              const cuuint64_t*, const cuuint64_t*,
                              const cuuint32_t*, const cuuint32_t*,
                              CUtensorMapInterleave, CUtensorMapSwizzle,
                              CUtensorMapL2promotion, CUtensorMapFloatOOBfill);

static void encode_map3(PFN_tmEnc enc, CUtensorMap* m, void* base, uint64_t rows) {
    cuuint64_t dims[3]    = {(cuuint64_t)cfg::K, (cuuint64_t)rows, 1};
    cuuint64_t strides[2] = {(cuuint64_t)cfg::K * 2, (cuuint64_t)rows * cfg::K * 2};
    cuuint32_t box[3]     = {64, 128, 1};            // 64 bf16 = 128B = SW128 atom
    cuuint32_t estr[3]    = {1, 1, 1};
    enc(m, CU_TENSOR_MAP_DATA_TYPE_BFLOAT16, 3, base, dims, strides, box, estr,
        CU_TENSOR_MAP_INTERLEAVE_NONE, CU_TENSOR_MAP_SWIZZLE_128B,
        CU_TENSOR_MAP_L2_PROMOTION_L2_128B, CU_TENSOR_MAP_FLOAT_OOB_FILL_NONE);
}

extern "C" void kernel_launch(void* const* d_in, const int* in_sizes, int n_in,
                              void* d_out, int out_size) {
    using namespace cfg;
    const float* x = nullptr; const void* q = nullptr; const float* scale = nullptr;
    const float* bias = nullptr; const float* la = nullptr; const float* lb = nullptr;
    for (int i = 0; i < n_in; i++) {
        switch (in_sizes[i]) {
            case 33554432: x = (const float*)d_in[i]; break;        // 8192*4096
            case 16777216: q = d_in[i]; break;                      // 4096*4096
            case 135168:   scale = (const float*)d_in[i]; break;    // 33*4096
            case 4096:     bias = (const float*)d_in[i]; break;
            case 32768:                                             // lora_a then lora_b
                if (!la) la = (const float*)d_in[i];
                else     lb = (const float*)d_in[i];
                break;
            default: break;
        }
    }
    float* out = (float*)d_out;

    // TMA tensormaps (driver entry point; no -lcuda needed)
    void* fn = nullptr;
    cudaDriverEntryPointQueryResult qres;
    cudaGetDriverEntryPoint("cuTensorMapEncodeTiled", &fn, cudaEnableDefault, &qres);
    PFN_tmEnc enc = (PFN_tmEnc)fn;
    void *xsym = nullptr, *wsym = nullptr;
    cudaGetSymbolAddress(&xsym, g_X);
    cudaGetSymbolAddress(&wsym, g_Wt);
    CUtensorMap tma_a, tma_b;
    encode_map3(enc, &tma_a, xsym, M);
    encode_map3(enc, &tma_b, wsym, N);

    k_dequant_t<<<dim3(N / 64, K / 64), 256>>>((const int*)q, scale);
    k_lora_conv<<<M / 32, 128>>>(x, la);

    cudaFuncSetAttribute(k_gemm, cudaFuncAttributeMaxDynamicSharedMemorySize, SMEM_TOTAL);
    k_gemm<<<dim3(4, NGROUPS), NTHREADS, SMEM_TOTAL>>>(tma_a, tma_b, bias, lb, out);
}

// round 16
// speedup vs baseline: 1.1045x; 1.1018x over previous
#include <cuda_runtime.h>
#include <cuda.h>
#include <cuda_bf16.h>
#include <cstdint>

// Arch-feature gate: tcgen05/TMA path only in the sm_103a cubin pass. The
// compute_103 PTX pass compiles the mma.sync fallback (never executed).
#if defined(__CUDA_ARCH__) && defined(__CUDA_ARCH_HAS_FEATURE__)
#if __CUDA_ARCH_HAS_FEATURE__(SM103_ALL)
#define HAS_TC 1
#else
#define HAS_TC 0
#endif
#else
#define HAS_TC 0
#endif

// ---------------- problem dims (fixed by setup_inputs) ----------------
namespace cfg {
constexpr int M = 8192;     // B*S
constexpr int N = 4096;     // D_OUT
constexpr int K = 4096;     // D_IN
constexpr int BM = 256, BN = 256, BK = 64;       // per 2-CTA pair
constexpr int STAGES = 5;
constexpr int NK = K / BK;                       // 64
constexpr int NT_N = N / BN;                     // 16
constexpr int NTILES = (M / BM) * NT_N;          // 512
constexpr int NPAIRS = 74;                       // 148 SMs / 2
constexpr int GEMM_CTAS = 2 * NPAIRS;            // 148
constexpr int LORA_BLOCKS = M / 32;              // 256
constexpr int A_SLICE = 128 * BK * 2;            // 16384 (per-CTA A rows)
constexpr int B_SLICE = 128 * BK * 2;            // 16384 (per-CTA B rows, N/2)
constexpr int STAGE_BYTES = A_SLICE + B_SLICE;   // 32768
constexpr int SMEM_TILE = 1024;
constexpr int SMEM_EPI  = SMEM_TILE + STAGES * STAGE_BYTES;   // 164864
constexpr int SMEM_LBS  = SMEM_EPI + 8 * 32 * 33 * 4;         // 198656
constexpr int SMEM_TOTAL = SMEM_LBS + 8 * 288 * 4;            // 207872
constexpr int MBAR_FULL = 64;                    // 5 x 8B
constexpr int MBAR_DONE = 112;                   // 5 x 8B
constexpr int MBAR_FIN  = 160;                   // 2 x 8B
constexpr int MBAR_EPI  = 176;                   // 2 x 8B
constexpr int NTHREADS = 320;                    // 8 epi warps + consumer + producer
// cg2 idesc: M_TOTAL=256 x N=256 kind::f16 bf16
constexpr uint32_t IDESC = 0x10u | 0x80u | 0x400u | ((256 / 8) << 17) | ((256 / 16) << 24);
}

// ---------------- scratch ----------------
__device__ __nv_bfloat16 g_X [(size_t)cfg::M * cfg::K];   // x in bf16, [M][K]
__device__ __nv_bfloat16 g_Wt[(size_t)cfg::N * cfg::K];   // W^T bf16, [N][K] K-major
__device__ float         g_H [cfg::M * 8];                // LoRA hidden
// PDL safety (monotonic across graph replays; no reset needed):
__device__ unsigned long long g_lora_blocks;   // lora block completions
__device__ unsigned long long g_lora_epoch;    // +1 per full lora pass
__device__ unsigned long long g_gemm_tickets;  // gemm CTA tickets

__constant__ float c_nf4[16] = {
    -1.0f, -0.6962f, -0.5251f, -0.3949f, -0.2844f, -0.1848f, -0.0911f, 0.0f,
     0.0796f, 0.1609f, 0.2461f, 0.3379f, 0.4407f, 0.5626f, 0.723f, 1.0f};

// ---------------- generic helpers ----------------
__device__ __forceinline__ uint32_t smem_u32(const void* p) {
    return (uint32_t)__cvta_generic_to_shared(p);
}
__device__ __forceinline__ void cp_async16(uint32_t s, const void* g) {
    asm volatile("cp.async.cg.shared.global [%0], [%1], 16;" :: "r"(s), "l"(g));
}
__device__ __forceinline__ void cp_commit() { asm volatile("cp.async.commit_group;"); }
template <int W>
__device__ __forceinline__ void cp_wait() {
    asm volatile("cp.async.wait_group %0;" :: "n"(W));
}
__device__ __forceinline__ uint32_t sw128(uint32_t b) { return b ^ ((b >> 3) & 0x70); }

__device__ __forceinline__ void ldsm_x4(uint32_t a[4], uint32_t addr) {
    asm volatile("ldmatrix.sync.aligned.m8n8.x4.shared.b16 {%0,%1,%2,%3}, [%4];"
                 : "=r"(a[0]), "=r"(a[1]), "=r"(a[2]), "=r"(a[3]) : "r"(addr));
}
__device__ __forceinline__ void mma16816(float d[4], const uint32_t a[4],
                                         uint32_t b0, uint32_t b1) {
    asm volatile(
        "mma.sync.aligned.m16n8k16.row.col.f32.bf16.bf16.f32 "
        "{%0,%1,%2,%3}, {%4,%5,%6,%7}, {%8,%9}, {%0,%1,%2,%3};"
        : "+f"(d[0]), "+f"(d[1]), "+f"(d[2]), "+f"(d[3])
        : "r"(a[0]), "r"(a[1]), "r"(a[2]), "r"(a[3]), "r"(b0), "r"(b1));
}

#if HAS_TC
// ---------------- tcgen05/TMA helpers (sm_103a pass only) ----------------
__device__ __forceinline__ uint64_t make_desc(uint32_t addr) {
    constexpr uint64_t BASE =
        (uint64_t(2) << 61) | (uint64_t(1) << 46) | (uint64_t(64) << 32) | (uint64_t(1) << 16);
    return BASE | ((uint64_t)(addr >> 4) & 0x3FFF);
}
__device__ __forceinline__ void mma_f16_ss_cg2(uint32_t d, uint64_t a, uint64_t b,
                                               uint32_t idesc, uint32_t en) {
    asm volatile(
        "{\n\t.reg .pred p;\n\tsetp.ne.u32 p, %5, 0;\n\t"
        "tcgen05.mma.cta_group::2.kind::f16 [%0], %1, %2, %3, "
        "{%4, %4, %4, %4, %4, %4, %4, %4}, p;\n\t}"
        :: "r"(d), "l"(a), "l"(b), "r"(idesc), "r"(0u), "r"(en) : "memory");
}
__device__ __forceinline__ void tc_commit_mc_cg2(uint32_t mbar, uint16_t mask) {
    asm volatile(
        "tcgen05.commit.cta_group::2.mbarrier::arrive::one.shared::cluster"
        ".multicast::cluster.b64 [%0], %1;"
        :: "r"(mbar), "h"(mask) : "memory");
}
__device__ __forceinline__ void mbar_init(uint32_t mbar, uint32_t cnt) {
    asm volatile("mbarrier.init.shared.b64 [%0], %1;" :: "r"(mbar), "r"(cnt) : "memory");
}
__device__ __forceinline__ void mbar_expect_tx(uint32_t mbar, uint32_t bytes) {
    asm volatile("mbarrier.arrive.expect_tx.shared.b64 _, [%0], %1;"
                 :: "r"(mbar), "r"(bytes) : "memory");
}
__device__ __forceinline__ void mbar_arrive_leader(uint32_t mbar) {
    asm volatile(
        "{\n\t.reg .b32 la;\n\tand.b32 la, %0, 0xFEFFFFFF;\n\t"
        "mbarrier.arrive.shared::cluster.b64 _, [la];\n\t}"
        :: "r"(mbar) : "memory");
}
__device__ __forceinline__ void mbar_wait(uint32_t mbar, uint32_t parity) {
    uint32_t done;
    asm volatile(
        "{\n\t.reg .pred p;\n\t"
        "mbarrier.try_wait.parity.acquire.cta.shared::cta.b64 p, [%1], %2;\n\t"
        "selp.b32 %0, 1, 0, p;\n\t}"
        : "=r"(done) : "r"(mbar), "r"(parity) : "memory");
    if (!done) {
        asm volatile(
            "{\n\t.reg .pred P1;\n\t"
            "WAIT_LOOP_%=:\n\t"
            "mbarrier.try_wait.parity.acquire.cta.shared::cta.b64 P1, [%0], %1, 0x989680;\n\t"
            "@P1 bra.uni WAIT_DONE_%=;\n\t"
            "bra.uni WAIT_LOOP_%=;\n\t"
            "WAIT_DONE_%=:\n\t}"
            :: "r"(mbar), "r"(parity) : "memory");
    }
}
// cg2 TMA: both CTAs execute; complete_tx targets the PAIR LEADER's barrier.
__device__ __forceinline__ void tma_load_3d_cg2(uint32_t smem_addr, const void* map,
                                                int cx, int cy, int cz, uint32_t mbar) {
    asm volatile(
        "{\n\t.reg .b32 lb;\n\t"
        "and.b32 lb, %5, 0xFEFFFFFF;\n\t"
        "cp.async.bulk.tensor.3d.cta_group::2.shared::cluster.global"
        ".tile.mbarrier::complete_tx::bytes [%0], [%1, {%2, %3, %4}], [lb];\n\t}"
        :: "r"(smem_addr), "l"(map), "r"(cx), "r"(cy), "r"(cz), "r"(mbar) : "memory");
}
__device__ __forceinline__ void fence_proxy_async_cta() {
    asm volatile("fence.proxy.async.shared::cta;" ::: "memory");
}
__device__ __forceinline__ void cluster_sync() {
    asm volatile("barrier.cluster.arrive.aligned;" ::: "memory");
    asm volatile("barrier.cluster.wait.aligned;" ::: "memory");
}
__device__ __forceinline__ uint32_t ctarank() {
    uint32_t r; asm("mov.u32 %0, %%cluster_ctarank;" : "=r"(r)); return r;
}
__device__ __forceinline__ void tc_fence_after() {
    asm volatile("tcgen05.fence::after_thread_sync;" ::: "memory");
}
__device__ __forceinline__ void tc_fence_before() {
    asm volatile("tcgen05.fence::before_thread_sync;" ::: "memory");
}
__device__ __forceinline__ void tc_wait_ld() {
    asm volatile("tcgen05.wait::ld.sync.aligned;" ::: "memory");
}
__device__ __forceinline__ void ldtm_x32(uint32_t* r, uint32_t tmem_addr) {
    asm volatile(
        "tcgen05.ld.sync.aligned.32x32b.x32.b32 "
        "{%0, %1, %2, %3, %4, %5, %6, %7, "
        " %8, %9, %10, %11, %12, %13, %14, %15, "
        " %16, %17, %18, %19, %20, %21, %22, %23, "
        " %24, %25, %26, %27, %28, %29, %30, %31}, [%32];"
        : "=r"(r[0]),  "=r"(r[1]),  "=r"(r[2]),  "=r"(r[3]),
          "=r"(r[4]),  "=r"(r[5]),  "=r"(r[6]),  "=r"(r[7]),
          "=r"(r[8]),  "=r"(r[9]),  "=r"(r[10]), "=r"(r[11]),
          "=r"(r[12]), "=r"(r[13]), "=r"(r[14]), "=r"(r[15]),
          "=r"(r[16]), "=r"(r[17]), "=r"(r[18]), "=r"(r[19]),
          "=r"(r[20]), "=r"(r[21]), "=r"(r[22]), "=r"(r[23]),
          "=r"(r[24]), "=r"(r[25]), "=r"(r[26]), "=r"(r[27]),
          "=r"(r[28]), "=r"(r[29]), "=r"(r[30]), "=r"(r[31])
        : "r"(tmem_addr));
}
#endif  // HAS_TC

// ---------------- 1) LoRA hidden H = x @ lora_a AND x -> bf16 (R13 best) ----
// PDL primary: fires launch_dependents at entry so the (independent) dequant
// kernel can start concurrently. Completion is published via monotonic epoch.
__global__ void __launch_bounds__(128) k_lora_conv(
    const float* __restrict__ x, const float* __restrict__ la) {
    using namespace cfg;
    asm volatile("griddepcontrol.launch_dependents;");
    const int warp = threadIdx.x >> 5, lane = threadIdx.x & 31;
    const int m0 = blockIdx.x * 32 + warp * 8;
    float acc[8][8];
#pragma unroll
    for (int i = 0; i < 8; i++)
#pragma unroll
        for (int j = 0; j < 8; j++) acc[i][j] = 0.0f;

    for (int it = 0; it < K / 128; it++) {
        const int k = it * 128 + lane * 4;
        const float4* lap = reinterpret_cast<const float4*>(la + (size_t)k * 8);
        float4 a[8];
#pragma unroll
        for (int j = 0; j < 8; j++) a[j] = lap[j];
#pragma unroll
        for (int rr = 0; rr < 8; rr++) {
            const size_t off = (size_t)(m0 + rr) * K + k;
            float4 xv = *reinterpret_cast<const float4*>(x + off);
            __nv_bfloat162 b0 = __floats2bfloat162_rn(xv.x, xv.y);
            __nv_bfloat162 b1 = __floats2bfloat162_rn(xv.z, xv.w);
            uint2 pk;
            pk.x = *reinterpret_cast<uint32_t*>(&b0);
            pk.y = *reinterpret_cast<uint32_t*>(&b1);
            *reinterpret_cast<uint2*>(g_X + off) = pk;
            acc[rr][0] += xv.x * a[0].x + xv.y * a[2].x + xv.z * a[4].x + xv.w * a[6].x;
            acc[rr][1] += xv.x * a[0].y + xv.y * a[2].y + xv.z * a[4].y + xv.w * a[6].y;
            acc[rr][2] += xv.x * a[0].z + xv.y * a[2].z + xv.z * a[4].z + xv.w * a[6].z;
            acc[rr][3] += xv.x * a[0].w + xv.y * a[2].w + xv.z * a[4].w + xv.w * a[6].w;
            acc[rr][4] += xv.x * a[1].x + xv.y * a[3].x + xv.z * a[5].x + xv.w * a[7].x;
            acc[rr][5] += xv.x * a[1].y + xv.y * a[3].y + xv.z * a[5].y + xv.w * a[7].y;
            acc[rr][6] += xv.x * a[1].z + xv.y * a[3].z + xv.z * a[5].z + xv.w * a[7].z;
            acc[rr][7] += xv.x * a[1].w + xv.y * a[3].w + xv.z * a[5].w + xv.w * a[7].w;
        }
    }
#pragma unroll
    for (int rr = 0; rr < 8; rr++)
#pragma unroll
        for (int r = 0; r < 8; r++) {
            float v = acc[rr][r];
#pragma unroll
            for (int off = 16; off; off >>= 1)
                v += __shfl_xor_sync(0xffffffffu, v, off);
            if (lane == 0) g_H[(m0 + rr) * 8 + r] = v;
        }
    // publish completion (monotonic; replay-safe)
    __threadfence();
    __syncthreads();
    if (threadIdx.x == 0) {
        unsigned long long d = atomicAdd(&g_lora_blocks, 1ULL);
        if ((d % (unsigned long long)LORA_BLOCKS) == (unsigned long long)(LORA_BLOCKS - 1))
            atomicAdd(&g_lora_epoch, 1ULL);
    }
}

// ---------------- 2) NF4 dequant + transpose: g_Wt[n][k] (R13 best) ----------
// PDL secondary: launched with programmaticStreamSerialization so it overlaps
// k_lora_conv (fully independent data).
__global__ void __launch_bounds__(256) k_dequant_t(
    const int* __restrict__ q, const float* __restrict__ scale) {
    using namespace cfg;
    __shared__ __nv_bfloat16 t[64][66];
    __shared__ int s_is32;
    const int k0 = blockIdx.y * 64;
    const int n0 = blockIdx.x * 64;
    const int tid = threadIdx.x;

    if (tid < 32) {
        int4 w = reinterpret_cast<const int4*>(q)[tid];
        bool ok = ((unsigned)(w.x + 8) < 16u) && ((unsigned)(w.y + 8) < 16u) &&
                  ((unsigned)(w.z + 8) < 16u) && ((unsigned)(w.w + 8) < 16u);
        unsigned b = __ballot_sync(0xffffffffu, ok);
        if (tid == 0) s_is32 = (b == 0xffffffffu);
    }
    __syncthreads();
    const bool is32 = (s_is32 != 0);

    if (is32) {
        for (int idx = tid; idx < 64 * 16; idx += 256) {
            int kk = idx >> 4, n4 = idx & 15;
            const size_t row = (size_t)(k0 + kk) * N + n0;
            int4 c = *(reinterpret_cast<const int4*>(q + row) + n4);
            float4 s = *reinterpret_cast<const float4*>(
                scale + (size_t)((k0 + kk) >> 7) * N + n0 + n4 * 4);
            t[kk][n4 * 4 + 0] = __hmul(__float2bfloat16(c_nf4[c.x + 8]), __float2bfloat16(s.x));
            t[kk][n4 * 4 + 1] = __hmul(__float2bfloat16(c_nf4[c.y + 8]), __float2bfloat16(s.y));
            t[kk][n4 * 4 + 2] = __hmul(__float2bfloat16(c_nf4[c.z + 8]), __float2bfloat16(s.z));
            t[kk][n4 * 4 + 3] = __hmul(__float2bfloat16(c_nf4[c.w + 8]), __float2bfloat16(s.w));
        }
    } else {
        for (int idx = tid; idx < 64 * 64; idx += 256) {
            int kk = idx >> 6, nn = idx & 63;
            int code = (int)((const signed char*)q)[(size_t)(k0 + kk) * N + n0 + nn] + 8;
            float s = scale[(size_t)((k0 + kk) >> 7) * N + n0 + nn];
            t[kk][nn] = __hmul(__float2bfloat16(c_nf4[code]), __float2bfloat16(s));
        }
    }
    __syncthreads();
#pragma unroll
    for (int it = 0; it < 2; it++) {
        int idx = tid + it * 256;
        int nn = idx >> 3, kg = idx & 7;
        __nv_bfloat162 p[4];
#pragma unroll
        for (int i = 0; i < 4; i++)
            p[i] = __halves2bfloat162(t[kg * 8 + 2 * i][nn], t[kg * 8 + 2 * i + 1][nn]);
        uint4 v;
        v.x = *reinterpret_cast<uint32_t*>(&p[0]);
        v.y = *reinterpret_cast<uint32_t*>(&p[1]);
        v.z = *reinterpret_cast<uint32_t*>(&p[2]);
        v.w = *reinterpret_cast<uint32_t*>(&p[3]);
        *reinterpret_cast<uint4*>(g_Wt + (size_t)(n0 + nn) * K + k0 + kg * 8) = v;
    }
}

// ---------------- 3) main GEMM: persistent cg2 pairs (R13 best) -------------
__global__ void __launch_bounds__(cfg::NTHREADS, 1) __cluster_dims__(2, 1, 1) k_gemm(
    const __grid_constant__ CUtensorMap tma_a,    // g_X,  box {64,128,1}
    const __grid_constant__ CUtensorMap tma_b,    // g_Wt, box {64,128,1}
    const float* __restrict__ bias,
    const float* __restrict__ lb,      // lora_b [8][N]
    float* __restrict__ out) {
    using namespace cfg;
    extern __shared__ __align__(1024) char smem[];
    const uint32_t sbase = smem_u32(smem);
    const int tid  = threadIdx.x;
    const int warp = tid >> 5, lane = tid & 31;
    const int pair = blockIdx.y;

    // PDL safety guard: ensure this replay's lora pass is complete (the graph
    // edge only guarantees dequant completion). Replay-safe via monotonic
    // tickets: CTA ticket t -> replay index t/GEMM_CTAS -> need epoch >= R+1.
    if (tid == 0) {
        unsigned long long t = atomicAdd(&g_gemm_tickets, 1ULL);
        unsigned long long target = t / (unsigned long long)GEMM_CTAS + 1ULL;
        while (atomicAdd(&g_lora_epoch, 0ULL) < target) {}
        __threadfence();
    }
    __syncthreads();

#if HAS_TC
    const uint32_t rank = ctarank();
    const uint16_t MASK = 0x3;

    if (warp == 8) {
        asm volatile("tcgen05.alloc.cta_group::2.sync.aligned.shared::cta.b32 [%0], %1;"
                     :: "r"(sbase), "r"(512u) : "memory");
        asm volatile("tcgen05.relinquish_alloc_permit.cta_group::2.sync.aligned;");
    }
    if (tid == 0) {
#pragma unroll
        for (int s = 0; s < STAGES; s++) {
            mbar_init(sbase + MBAR_FULL + s * 8, 1);
            mbar_init(sbase + MBAR_DONE + s * 8, 1);
        }
        mbar_init(sbase + MBAR_FIN + 0, 1);
        mbar_init(sbase + MBAR_FIN + 8, 1);
        mbar_init(sbase + MBAR_EPI + 0, 2);
        mbar_init(sbase + MBAR_EPI + 8, 2);
        fence_proxy_async_cta();
    }
    __syncthreads();
    cluster_sync();
    uint32_t tmem_base;
    asm volatile("ld.shared.b32 %0, [%1];" : "=r"(tmem_base) : "r"(sbase));

    if (tid == 288) {
        // ---------------- producer: continuous TMA ring across tiles --------
        int st = 0, ph = 0, g = 0;
        for (int ti = pair; ti < NTILES; ti += NPAIRS) {
            const int bm0 = (ti >> 4) * 256;
            const int bn0 = (ti & 15) * 256;
            for (int kt = 0; kt < NK; kt++) {
                if (g >= STAGES)
                    mbar_wait(sbase + MBAR_DONE + st * 8, ph ^ 1);
                uint32_t fullb = sbase + MBAR_FULL + st * 8;
                if (rank == 0)
                    mbar_expect_tx(fullb, (uint32_t)(2 * STAGE_BYTES));
                uint32_t s0 = sbase + SMEM_TILE + st * STAGE_BYTES;
                tma_load_3d_cg2(s0, &tma_a, kt * BK, bm0 + (int)rank * 128, 0, fullb);
                tma_load_3d_cg2(s0 + A_SLICE, &tma_b, kt * BK, bn0 + (int)rank * 128, 0, fullb);
                g++;
                if (++st == STAGES) { st = 0; ph ^= 1; }
            }
        }
    }
    if (rank == 0 && tid == 256) {
        // ---------------- consumer: MMA dispatch, double-buffered D ---------
        int st = 0, ph = 0;
        int tile_i = 0;
        for (int ti = pair; ti < NTILES; ti += NPAIRS, tile_i++) {
            const int buf = tile_i & 1;
            if (tile_i >= 2)
                mbar_wait(sbase + MBAR_EPI + buf * 8, ((tile_i - 2) >> 1) & 1);
            const uint32_t dbase = tmem_base + (uint32_t)buf * 256u;
            for (int kt = 0; kt < NK; kt++) {
                mbar_wait(sbase + MBAR_FULL + st * 8, ph);
                uint32_t s0 = sbase + SMEM_TILE + st * STAGE_BYTES;
                uint64_t ad = make_desc(s0);
                uint64_t bd = make_desc(s0 + A_SLICE);
#pragma unroll
                for (int ks = 0; ks < 4; ks++) {
                    uint32_t en = (kt > 0 || ks > 0) ? 1u : 0u;
                    mma_f16_ss_cg2(dbase, ad + ks * 2, bd + ks * 2, IDESC, en);
                }
                tc_commit_mc_cg2(sbase + MBAR_DONE + st * 8, MASK);
                if (++st == STAGES) { st = 0; ph ^= 1; }
            }
            tc_commit_mc_cg2(sbase + MBAR_FIN + buf * 8, MASK);
        }
    }
    if (tid < 256) {
        // ---------------- epilogue: drain buffer t while t+1 computes -------
        const int rg = warp & 3;           // TMEM subpartition (row group)
        const int ch = warp >> 2;          // column half (128 cols each)
        float* sc = reinterpret_cast<float*>(smem + SMEM_EPI) + warp * (32 * 33);
        float* st = reinterpret_cast<float*>(smem + SMEM_LBS) + warp * 288;
        int tile_i = 0;
        for (int ti = pair; ti < NTILES; ti += NPAIRS, tile_i++) {
            const int buf = tile_i & 1;
            const int bm0 = (ti >> 4) * 256;
            const int bn0 = (ti & 15) * 256;
            mbar_wait(sbase + MBAR_FIN + buf * 8, (tile_i >> 1) & 1);
            tc_fence_after();

            const int mrow = bm0 + (int)rank * 128 + rg * 32;
            const int m = mrow + lane;
            float4 ha = *reinterpret_cast<const float4*>(g_H + m * 8);
            float4 hb = *reinterpret_cast<const float4*>(g_H + m * 8 + 4);
            float h[8] = {ha.x, ha.y, ha.z, ha.w, hb.x, hb.y, hb.z, hb.w};
            const uint32_t dbase = tmem_base + (uint32_t)buf * 256u + ch * 128;

#pragma unroll
            for (int chunk = 0; chunk < 4; chunk++) {
                const int c0 = chunk * 32;
                uint32_t d[32];
                ldtm_x32(d, dbase + c0);
                const int n_base = bn0 + ch * 128 + c0;
                {
                    const int n = n_base + lane;
#pragma unroll
                    for (int rr = 0; rr < 8; rr++) st[rr * 32 + lane] = lb[rr * N + n];
                    st[256 + lane] = bias[n];
                }
                tc_wait_ld();
                __syncwarp();
#pragma unroll
                for (int r = 0; r < 32; r++) {
                    float delta = 0.0f;
#pragma unroll
                    for (int rr = 0; rr < 8; rr++) delta += h[rr] * st[rr * 32 + r];
                    __nv_bfloat16 bsum = __hadd(__float2bfloat16(__uint_as_float(d[r])),
                                                __float2bfloat16(st[256 + r]));
                    sc[lane * 33 + r] = __bfloat162float(bsum) + 2.0f * delta;
                }
                __syncwarp();
#pragma unroll
                for (int r = 0; r < 32; r++) {
                    out[(size_t)(mrow + r) * N + n_base + lane] = sc[r * 33 + lane];
                }
                __syncwarp();
            }
            tc_fence_before();
            asm volatile("bar.sync 1, 256;" ::: "memory");   // all 8 epi warps done
            if (tid == 0) mbar_arrive_leader(sbase + MBAR_EPI + buf * 8);
        }
    }
    __syncthreads();
    if (warp == 8) {
        asm volatile("tcgen05.dealloc.cta_group::2.sync.aligned.b32 %0, %1;"
                     :: "r"(tmem_base), "r"(512u));
    }
    cluster_sync();   // no CTA exits while peer cg2 traffic could be in flight

#else
    // ================= mma.sync fallback (compute_103 PTX pass only) =======
    (void)tma_a; (void)tma_b;
    constexpr int FB_A = 16384, FB_STAGE = 49152;
    uint32_t swoff[8], goff[8];
#pragma unroll
    for (int i = 0; i < 8; i++) {
        int c = (tid & 255) + i * 256;
        int row = c >> 3, col = c & 7;
        swoff[i] = sw128(row * 128 + col * 16);
        goff[i]  = (uint32_t)row * (K * 2) + col * 16;
    }
    const int wm = warp >> 2;
    const int wn = warp & 3;
    const int rankf = blockIdx.x & 1;

    for (int ti = pair; ti < NTILES; ti += NPAIRS) {
        const int bm0f = (ti >> 4) * 256 + rankf * 128;
        const int bn0  = (ti & 15) * 256;

        auto fb_loads = [&](int kt, int stg) {
            const char* gA = reinterpret_cast<const char*>(g_X)
                + (size_t)bm0f * (K * 2) + (size_t)kt * (BK * 2);
            const char* gB = reinterpret_cast<const char*>(g_Wt)
                + (size_t)bn0 * (K * 2) + (size_t)kt * (BK * 2);
            uint32_t sA = sbase + SMEM_TILE + stg * FB_STAGE;
            uint32_t sB = sA + FB_A;
#pragma unroll
            for (int i = 0; i < 4; i++) cp_async16(sA + swoff[i], gA + goff[i]);
#pragma unroll
            for (int i = 0; i < 8; i++) cp_async16(sB + swoff[i], gB + goff[i]);
        };

        float acc[4][8][4];
#pragma unroll
        for (int i = 0; i < 4; i++)
#pragma unroll
            for (int j = 0; j < 8; j++)
#pragma unroll
                for (int e = 0; e < 4; e++) acc[i][j][e] = 0.0f;

        if (tid < 256) { fb_loads(0, 0); }
        cp_commit();
        if (tid < 256) { fb_loads(1, 1); }
        cp_commit();

        for (int kt = 0; kt < NK; kt++) {
            const int stg = kt % 3;
            cp_wait<1>();
            __syncthreads();
            const int kn = kt + 2;
            if (kn < NK && tid < 256) fb_loads(kn, kn % 3);
            cp_commit();

            if (tid < 256) {
                const uint32_t aST = sbase + SMEM_TILE + stg * FB_STAGE;
                const uint32_t bST = aST + FB_A;
#pragma unroll
                for (int ks = 0; ks < 4; ks++) {
                    uint32_t afrag[4][4], bfrag[4][4];
#pragma unroll
                    for (int mt = 0; mt < 4; mt++) {
                        int row = wm * 64 + mt * 16 + (lane & 15);
                        ldsm_x4(afrag[mt], aST + sw128(row * 128 + ks * 32 + (lane >> 4) * 16));
                    }
#pragma unroll
                    for (int nt = 0; nt < 4; nt++) {
                        int row = wn * 64 + nt * 16 + (lane & 15);
                        ldsm_x4(bfrag[nt], bST + sw128(row * 128 + ks * 32 + (lane >> 4) * 16));
                    }
#pragma unroll
                    for (int mt = 0; mt < 4; mt++)
#pragma unroll
                        for (int nt = 0; nt < 4; nt++) {
                            mma16816(acc[mt][2 * nt],     afrag[mt], bfrag[nt][0], bfrag[nt][2]);
                            mma16816(acc[mt][2 * nt + 1], afrag[mt], bfrag[nt][1], bfrag[nt][3]);
                        }
                }
            }
            __syncthreads();
        }

        if (tid < 256) {
            const int mrow = lane >> 2;
            const int ncol = (lane & 3) * 2;
#pragma unroll
            for (int mt = 0; mt < 4; mt++) {
                int m0 = bm0f + wm * 64 + mt * 16 + mrow;
                const float4* h0p = reinterpret_cast<const float4*>(g_H + m0 * 8);
                const float4* h1p = reinterpret_cast<const float4*>(g_H + (m0 + 8) * 8);
                float4 h0a = h0p[0], h0b = h0p[1];
                float4 h1a = h1p[0], h1b = h1p[1];
                float h0r[8] = {h0a.x, h0a.y, h0a.z, h0a.w, h0b.x, h0b.y, h0b.z, h0b.w};
                float h1r[8] = {h1a.x, h1a.y, h1a.z, h1a.w, h1b.x, h1b.y, h1b.z, h1b.w};
#pragma unroll
                for (int nt = 0; nt < 8; nt++) {
                    int n0 = bn0 + wn * 64 + nt * 8 + ncol;
                    float d00 = 0.f, d01 = 0.f, d10 = 0.f, d11 = 0.f;
#pragma unroll
                    for (int r = 0; r < 8; r++) {
                        float l0 = lb[r * N + n0];
                        float l1 = lb[r * N + n0 + 1];
                        d00 += h0r[r] * l0;  d01 += h0r[r] * l1;
                        d10 += h1r[r] * l0;  d11 += h1r[r] * l1;
                    }
                    __nv_bfloat16 bb0 = __float2bfloat16(bias[n0]);
                    __nv_bfloat16 bb1 = __float2bfloat16(bias[n0 + 1]);
                    float o00 = __bfloat162float(__hadd(__float2bfloat16(acc[mt][nt][0]), bb0)) + 2.0f * d00;
                    float o01 = __bfloat162float(__hadd(__float2bfloat16(acc[mt][nt][1]), bb1)) + 2.0f * d01;
                    float o10 = __bfloat162float(__hadd(__float2bfloat16(acc[mt][nt][2]), bb0)) + 2.0f * d10;
                    float o11 = __bfloat162float(__hadd(__float2bfloat16(acc[mt][nt][3]), bb1)) + 2.0f * d11;
                    *reinterpret_cast<float2*>(out + (size_t)m0 * N + n0)       = make_float2(o00, o01);
                    *reinterpret_cast<float2*>(out + (size_t)(m0 + 8) * N + n0) = make_float2(o10, o11);
                }
            }
        }
        __syncthreads();
    }
#endif
}

// ---------------- launch ----------------
typedef CUresult (*PFN_tmEnc)(CUtensorMap*, CUtensorMapDataType, cuuint32_t, void*,
                              const cuuint64_t*, const cuuint64_t*,
                              const cuuint32_t*, const cuuint32_t*,
                              CUtensorMapInterleave, CUtensorMapSwizzle,
                              CUtensorMapL2promotion, CUtensorMapFloatOOBfill);

static void encode_map3(PFN_tmEnc enc, CUtensorMap* m, void* base, uint64_t rows) {
    cuuint64_t dims[3]    = {(cuuint64_t)cfg::K, (cuuint64_t)rows, 1};
    cuuint64_t strides[2] = {(cuuint64_t)cfg::K * 2, (cuuint64_t)rows * cfg::K * 2};
    cuuint32_t box[3]     = {64, 128, 1};            // 64 bf16 = 128B = SW128 atom
    cuuint32_t estr[3]    = {1, 1, 1};
    enc(m, CU_TENSOR_MAP_DATA_TYPE_BFLOAT16, 3, base, dims, strides, box, estr,
        CU_TENSOR_MAP_INTERLEAVE_NONE, CU_TENSOR_MAP_SWIZZLE_128B,
        CU_TENSOR_MAP_L2_PROMOTION_L2_128B, CU_TENSOR_MAP_FLOAT_OOB_FILL_NONE);
}

extern "C" void kernel_launch(void* const* d_in, const int* in_sizes, int n_in,
                              void* d_out, int out_size) {
    using namespace cfg;
    const float* x = nullptr; const void* q = nullptr; const float* scale = nullptr;
    const float* bias = nullptr; const float* la = nullptr; const float* lb = nullptr;
    for (int i = 0; i < n_in; i++) {
        switch (in_sizes[i]) {
            case 33554432: x = (const float*)d_in[i]; break;        // 8192*4096
            case 16777216: q = d_in[i]; break;                      // 4096*4096
            case 135168:   scale = (const float*)d_in[i]; break;    // 33*4096
            case 4096:     bias = (const float*)d_in[i]; break;
            case 32768:                                             // lora_a then lora_b
                if (!la) la = (const float*)d_in[i];
                else     lb = (const float*)d_in[i];
                break;
            default: break;
        }
    }
    float* out = (float*)d_out;

    // TMA tensormaps (driver entry point; no -lcuda needed)
    void* fn = nullptr;
    cudaDriverEntryPointQueryResult qres;
    cudaGetDriverEntryPoint("cuTensorMapEncodeTiled", &fn, cudaEnableDefault, &qres);
    PFN_tmEnc enc = (PFN_tmEnc)fn;
    void *xsym = nullptr, *wsym = nullptr;
    cudaGetSymbolAddress(&xsym, g_X);
    cudaGetSymbolAddress(&wsym, g_Wt);
    CUtensorMap tma_a, tma_b;
    encode_map3(enc, &tma_a, xsym, M);
    encode_map3(enc, &tma_b, wsym, N);

    // 1) lora (PDL primary — fires launch_dependents at entry)
    k_lora_conv<<<M / 32, 128>>>(x, la);

    // 2) dequant (PDL secondary — starts while lora still runs; independent)
    {
        cudaLaunchConfig_t lc = {};
        lc.gridDim  = dim3(N / 64, K / 64);
        lc.blockDim = dim3(256);
        lc.dynamicSmemBytes = 0;
        cudaLaunchAttribute at[1];
        at[0].id = cudaLaunchAttributeProgrammaticStreamSerialization;
        at[0].val.programmaticStreamSerializationAllowed = 1;
        lc.attrs = at;
        lc.numAttrs = 1;
        cudaLaunchKernelEx(&lc, k_dequant_t, (const int*)q, scale);
    }

    // 3) GEMM (normal launch: waits dequant completion; lora guarded in-kernel)
    cudaFuncSetAttribute(k_gemm, cudaFuncAttributeMaxDynamicSharedMemorySize, SMEM_TOTAL);
    k_gemm<<<dim3(2, NPAIRS), NTHREADS, SMEM_TOTAL>>>(tma_a, tma_b, bias, lb, out);
}